// round 9
// baseline (speedup 1.0000x reference)
#include <cuda_runtime.h>
#include <cuda_bf16.h>
#include <math.h>
#include <stdint.h>

#define NB 2
#define NL 5000
#define HW 256
#define NPIX 65536
#define CIN 256
#define CL 128
#define PL 64
#define EPSB 1e-5f

typedef unsigned long long ull;

// ---------------- device scratch (no allocations allowed) ----------------
__device__ float g_xbuf[(size_t)NB * NPIX * CL];   // fc1 output, [b][h][w][c] fp32 (64 MB)
__device__ uint2 g_fc1p[8 * 16 * 128];             // fc1_w (hi,lo) bf16x2, [chunk][kpair][o]
__device__ float g_a1[CL], g_b1c[CL];              // BN1 fold
__device__ float2 g_w1p[(CL / 2) * PL];            // conv1 (BN2 folded), [cpair][o]
__device__ float g_b1f[PL];
__device__ float4 g_w2q[PL * PL];                  // conv2 (BN3 folded), [i][o] -> (w0,w1,w2,0)
__device__ float g_b2f[PL];
__device__ float2 g_w3p[(PL / 2) * CL];            // conv3, [ipair][o]

// ---------------- helpers ----------------
__device__ __forceinline__ ull pk2(float lo, float hi) {
    ull r; asm("mov.b64 %0, {%1, %2};" : "=l"(r) : "f"(lo), "f"(hi)); return r;
}
__device__ __forceinline__ void upk2(ull v, float& lo, float& hi) {
    asm("mov.b64 {%0, %1}, %2;" : "=f"(lo), "=f"(hi) : "l"(v));
}
__device__ __forceinline__ void fma2(ull& d, ull a, ull b) {
    asm("fma.rn.f32x2 %0, %1, %2, %0;" : "+l"(d) : "l"(a), "l"(b));
}
// bf16 2-term split of a pair (x -> lane0, y -> lane1)
__device__ __forceinline__ void sp2(float x, float y, uint32_t& h, uint32_t& l) {
    __nv_bfloat162 hb = __floats2bfloat162_rn(x, y);
    float lx = x - __low2float(hb);
    float ly = y - __high2float(hb);
    __nv_bfloat162 lb = __floats2bfloat162_rn(lx, ly);
    h = *reinterpret_cast<uint32_t*>(&hb);
    l = *reinterpret_cast<uint32_t*>(&lb);
}
__device__ __forceinline__ void mma_bf16(float* d, uint32_t a0, uint32_t a1,
                                         uint32_t a2, uint32_t a3,
                                         uint32_t b0, uint32_t b1) {
    asm volatile(
        "mma.sync.aligned.m16n8k16.row.col.f32.bf16.bf16.f32 "
        "{%0,%1,%2,%3}, {%4,%5,%6,%7}, {%8,%9}, {%0,%1,%2,%3};\n"
        : "+f"(d[0]), "+f"(d[1]), "+f"(d[2]), "+f"(d[3])
        : "r"(a0), "r"(a1), "r"(a2), "r"(a3), "r"(b0), "r"(b1));
}

// ---------------- prep: fold BN, build packed weight tables ----------------
__global__ void prep_kernel(const float* __restrict__ fc1_w,
                            const float* __restrict__ bn1_g, const float* __restrict__ bn1_b,
                            const float* __restrict__ bn1_m, const float* __restrict__ bn1_v,
                            const float* __restrict__ conv1_w, const float* __restrict__ conv1_b,
                            const float* __restrict__ bn2_g, const float* __restrict__ bn2_b,
                            const float* __restrict__ bn2_m, const float* __restrict__ bn2_v,
                            const float* __restrict__ conv2_w, const float* __restrict__ conv2_b,
                            const float* __restrict__ bn3_g, const float* __restrict__ bn3_b,
                            const float* __restrict__ bn3_m, const float* __restrict__ bn3_v,
                            const float* __restrict__ conv3_w) {
    int tid = blockIdx.x * blockDim.x + threadIdx.x;
    int nt = gridDim.x * blockDim.x;
    for (int i = tid; i < CL; i += nt) {
        float a = bn1_g[i] * rsqrtf(bn1_v[i] + EPSB);
        g_a1[i] = a;
        g_b1c[i] = bn1_b[i] - bn1_m[i] * a;
    }
    for (int i = tid; i < PL; i += nt) {
        float a2 = bn2_g[i] * rsqrtf(bn2_v[i] + EPSB);
        g_b1f[i] = conv1_b[i] * a2 + bn2_b[i] - bn2_m[i] * a2;
        float a3 = bn3_g[i] * rsqrtf(bn3_v[i] + EPSB);
        g_b2f[i] = conv2_b[i] * a3 + bn3_b[i] - bn3_m[i] * a3;
    }
    for (int i = tid; i < (CL / 2) * PL; i += nt) {
        int cp = i / PL, o = i % PL;
        float a2 = bn2_g[o] * rsqrtf(bn2_v[o] + EPSB);
        g_w1p[i] = make_float2(conv1_w[o * CL + 2 * cp] * a2,
                               conv1_w[o * CL + 2 * cp + 1] * a2);
    }
    for (int i = tid; i < PL * PL; i += nt) {
        int ii = i / PL, o = i % PL;
        float a3 = bn3_g[o] * rsqrtf(bn3_v[o] + EPSB);
        const float* ws = conv2_w + (o * PL + ii) * 3;
        g_w2q[i] = make_float4(ws[0] * a3, ws[1] * a3, ws[2] * a3, 0.0f);
    }
    for (int i = tid; i < (PL / 2) * CL; i += nt) {
        int ip = i / CL, o = i % CL;
        g_w3p[i] = make_float2(conv3_w[o * PL + 2 * ip], conv3_w[o * PL + 2 * ip + 1]);
    }
    // fc1 weights: [chunk 8][kpair 16][o 128], (hi,lo) bf16x2 packed over adjacent k
    for (int i = tid; i < 8 * 16 * 128; i += nt) {
        int ch = i >> 11, kp = (i >> 7) & 15, o = i & 127;
        int k = ch * 32 + 2 * kp;
        uint32_t h, l;
        sp2(fc1_w[o * CIN + k], fc1_w[o * CIN + k + 1], h, l);
        g_fc1p[i] = make_uint2(h, l);
    }
}

// ---------------- fc1 via mma.sync bf16, (hi,lo)-interleaved A smem, B from L1 ----------------
// C[px, o] = F[px, c] * W[c, o]; output pixel-major xbuf[b][pix][o].
// CTA: 256 threads (8 warps, 2(m) x 4(n)). Tile M=128 px, N=128 o, K chunked by 32.
__global__ __launch_bounds__(256) void fc1_tc_kernel(const float* __restrict__ feature,
                                                     const float* __restrict__ fc1_b) {
    __shared__ uint2 Ax[16][136];      // [kpair][px], (hi,lo) bf16x2 per element
    __shared__ float biass[128];

    int tid = threadIdx.x;
    long p0l = (long)blockIdx.x * 128;
    int b = (int)(p0l >> 16);
    int pix0 = (int)(p0l & 65535);
    const float* fb = feature + (size_t)b * CIN * NPIX + pix0;

    if (tid < 128) biass[tid] = fc1_b[tid];

    int wid = tid >> 5, lane = tid & 31;
    int warp_m = wid >> 2, warp_n = wid & 3;
    int grp = lane >> 2, qid = lane & 3;
    int pxb = warp_m * 64;
    int ob  = warp_n * 32;

    float acc[4][4][4];
#pragma unroll
    for (int mt = 0; mt < 4; mt++)
#pragma unroll
        for (int nt = 0; nt < 4; nt++)
#pragma unroll
            for (int j = 0; j < 4; j++) acc[mt][nt][j] = 0.0f;

    int p2  = tid >> 4;          // 0..15 k-pair within chunk
    int px0 = (tid & 15) * 8;    // 8 px per thread

    // prefetch chunk 0 (rows c = 2*p2, 2*p2+1)
    float4 A0a, A0b, A1a, A1b;
    {
        const float* fa = fb + (size_t)(2 * p2) * NPIX + px0;
        A0a = *(const float4*)fa;          A0b = *(const float4*)(fa + 4);
        A1a = *(const float4*)(fa + NPIX); A1b = *(const float4*)(fa + NPIX + 4);
    }

    for (int ch = 0; ch < 8; ch++) {
        __syncthreads();
        {
            uint32_t h, l;
            sp2(A0a.x, A1a.x, h, l); Ax[p2][px0 + 0] = make_uint2(h, l);
            sp2(A0a.y, A1a.y, h, l); Ax[p2][px0 + 1] = make_uint2(h, l);
            sp2(A0a.z, A1a.z, h, l); Ax[p2][px0 + 2] = make_uint2(h, l);
            sp2(A0a.w, A1a.w, h, l); Ax[p2][px0 + 3] = make_uint2(h, l);
            sp2(A0b.x, A1b.x, h, l); Ax[p2][px0 + 4] = make_uint2(h, l);
            sp2(A0b.y, A1b.y, h, l); Ax[p2][px0 + 5] = make_uint2(h, l);
            sp2(A0b.z, A1b.z, h, l); Ax[p2][px0 + 6] = make_uint2(h, l);
            sp2(A0b.w, A1b.w, h, l); Ax[p2][px0 + 7] = make_uint2(h, l);
        }
        __syncthreads();
        if (ch < 7) {
            int c0 = (ch + 1) * 32;
            const float* fa = fb + (size_t)(c0 + 2 * p2) * NPIX + px0;
            A0a = *(const float4*)fa;          A0b = *(const float4*)(fa + 4);
            A1a = *(const float4*)(fa + NPIX); A1b = *(const float4*)(fa + NPIX + 4);
        }

#pragma unroll
        for (int ks = 0; ks < 2; ks++) {
            int r0 = ks * 8 + qid;
            const uint2* ar  = Ax[r0];
            const uint2* ar4 = Ax[r0 + 4];
            uint32_t ah[4][4], al[4][4];
#pragma unroll
            for (int mt = 0; mt < 4; mt++) {
                int px = pxb + mt * 16 + grp;
                uint2 e0 = ar[px], e1 = ar[px + 8], e2 = ar4[px], e3 = ar4[px + 8];
                ah[mt][0] = e0.x; ah[mt][1] = e1.x; ah[mt][2] = e2.x; ah[mt][3] = e3.x;
                al[mt][0] = e0.y; al[mt][1] = e1.y; al[mt][2] = e2.y; al[mt][3] = e3.y;
            }
            const uint2* bp  = g_fc1p + (ch * 16 + ks * 8 + qid) * 128;
            const uint2* bp4 = bp + 4 * 128;
#pragma unroll
            for (int nt = 0; nt < 4; nt++) {
                int oo = ob + nt * 8 + grp;
                uint2 b0 = __ldg(&bp[oo]);
                uint2 b4 = __ldg(&bp4[oo]);
#pragma unroll
                for (int mt = 0; mt < 4; mt++) {
                    mma_bf16(acc[mt][nt], ah[mt][0], ah[mt][1], ah[mt][2], ah[mt][3], b0.x, b4.x);
                    mma_bf16(acc[mt][nt], ah[mt][0], ah[mt][1], ah[mt][2], ah[mt][3], b0.y, b4.y);
                    mma_bf16(acc[mt][nt], al[mt][0], al[mt][1], al[mt][2], al[mt][3], b0.x, b4.x);
                }
            }
        }
    }

    // store fp32: c0=(r,2q) c1=(r,2q+1) c2=(r+8,2q) c3=(r+8,2q+1)
#pragma unroll
    for (int mt = 0; mt < 4; mt++) {
#pragma unroll
        for (int nt = 0; nt < 4; nt++) {
            int px = pix0 + pxb + mt * 16 + grp;
            int oo = ob + nt * 8 + qid * 2;
            float bx = biass[oo], by = biass[oo + 1];
            float2 r0 = make_float2(acc[mt][nt][0] + bx, acc[mt][nt][1] + by);
            float2 r1 = make_float2(acc[mt][nt][2] + bx, acc[mt][nt][3] + by);
            size_t base = ((size_t)b * NPIX + px) * CL + oo;
            *(float2*)&g_xbuf[base] = r0;
            *(float2*)&g_xbuf[base + (size_t)8 * CL] = r1;
        }
    }
}

// ---------------- per-line fused kernel (best-measured config, unchanged) ----------------
__global__ __launch_bounds__(128) void line_kernel(const float* __restrict__ lines,
                            const float* __restrict__ conv3_b,
                            const float* __restrict__ fc2_w,
                            const float* __restrict__ fc2_b,
                            float* __restrict__ out) {
    __shared__ int4   s_off[32];
    __shared__ float4 s_w[32];
    __shared__ float h0s[CL][8];
    __shared__ float h1s[PL][12];
    __shared__ float h2s[PL][8];
    __shared__ float red[4][3];

    int tid = threadIdx.x;
    int n = blockIdx.x;
    int b = n / NL;

    if (tid < 32) {
        int p = tid;
        float lam = (float)p * (1.0f / 31.0f);
        const float* lp = lines + (size_t)n * 4;
        float px = lp[0] * lam + lp[2] * (1.0f - lam) - 0.5f;
        float py = lp[1] * lam + lp[3] * (1.0f - lam) - 0.5f;
        float px0 = fminf(fmaxf(floorf(px), 0.0f), 255.0f);
        float py0 = fminf(fmaxf(floorf(py), 0.0f), 255.0f);
        float px1 = fminf(px0 + 1.0f, 255.0f);
        float py1 = fminf(py0 + 1.0f, 255.0f);
        int ix0 = (int)px0, iy0 = (int)py0, ix1 = (int)px1, iy1 = (int)py1;
        s_off[p] = make_int4((ix0 * HW + iy0) * CL, (ix1 * HW + iy0) * CL,
                             (ix0 * HW + iy1) * CL, (ix1 * HW + iy1) * CL);
        s_w[p] = make_float4((px1 - px) * (py1 - py), (px - px0) * (py1 - py),
                             (px1 - px) * (py - py0), (px - px0) * (py - py0));
    }
    for (int i = tid; i < PL * 12; i += 128) ((float*)h1s)[i] = 0.0f;
    __syncthreads();

    const float* xb = g_xbuf + (size_t)b * NPIX * CL + tid;
    float mx[8];
#pragma unroll
    for (int p = 0; p < 32; p++) {
        int4 off = s_off[p];
        float4 w = s_w[p];
        float v = w.x * __ldg(xb + off.x) + w.y * __ldg(xb + off.y)
                + w.z * __ldg(xb + off.z) + w.w * __ldg(xb + off.w);
        int g = p >> 2;
        if ((p & 3) == 0) mx[g] = v; else mx[g] = fmaxf(mx[g], v);
    }
    {
        float a1 = g_a1[tid], b1 = g_b1c[tid];
#pragma unroll
        for (int t = 0; t < 8; t++) h0s[tid][t] = fmaxf(mx[t] * a1 + b1, 0.0f);
    }
    __syncthreads();

    int o = tid & 63, th = tid >> 6, t0 = th * 4;
    {
        ull a01 = 0ULL, a23 = 0ULL;
#pragma unroll 8
        for (int cp = 0; cp < CL / 2; cp++) {
            ulonglong2 ha = *(const ulonglong2*)&h0s[2 * cp][t0];
            ulonglong2 hb = *(const ulonglong2*)&h0s[2 * cp + 1][t0];
            float2 w = __ldg(&g_w1p[cp * PL + o]);
            ull wx = pk2(w.x, w.x), wy = pk2(w.y, w.y);
            fma2(a01, ha.x, wx); fma2(a23, ha.y, wx);
            fma2(a01, hb.x, wy); fma2(a23, hb.y, wy);
        }
        float r0, r1, r2, r3;
        upk2(a01, r0, r1); upk2(a23, r2, r3);
        float bb = g_b1f[o];
        h1s[o][1 + t0 + 0] = fmaxf(r0 + bb, 0.0f);
        h1s[o][1 + t0 + 1] = fmaxf(r1 + bb, 0.0f);
        h1s[o][1 + t0 + 2] = fmaxf(r2 + bb, 0.0f);
        h1s[o][1 + t0 + 3] = fmaxf(r3 + bb, 0.0f);
    }
    __syncthreads();
    {
        ull a01 = 0ULL, a23 = 0ULL;
#pragma unroll 8
        for (int i = 0; i < PL; i++) {
            float4 hv = *(const float4*)&h1s[i][t0];
            float2 hv2 = *(const float2*)&h1s[i][t0 + 4];
            float4 w = __ldg(&g_w2q[i * PL + o]);
            ull wx = pk2(w.x, w.x), wy = pk2(w.y, w.y), wz = pk2(w.z, w.z);
            ull pxy = pk2(hv.x, hv.y), pyz = pk2(hv.y, hv.z), pzw = pk2(hv.z, hv.w);
            ull pw0 = pk2(hv.w, hv2.x), p01 = pk2(hv2.x, hv2.y);
            fma2(a01, pxy, wx); fma2(a01, pyz, wy); fma2(a01, pzw, wz);
            fma2(a23, pzw, wx); fma2(a23, pw0, wy); fma2(a23, p01, wz);
        }
        float r0, r1, r2, r3;
        upk2(a01, r0, r1); upk2(a23, r2, r3);
        float bb = g_b2f[o];
        h2s[o][t0 + 0] = fmaxf(r0 + bb, 0.0f);
        h2s[o][t0 + 1] = fmaxf(r1 + bb, 0.0f);
        h2s[o][t0 + 2] = fmaxf(r2 + bb, 0.0f);
        h2s[o][t0 + 3] = fmaxf(r3 + bb, 0.0f);
    }
    __syncthreads();
    float y[8];
    {
        ull acc[4] = {0ULL, 0ULL, 0ULL, 0ULL};
#pragma unroll 8
        for (int ip = 0; ip < PL / 2; ip++) {
            ulonglong2 h0lo = *(const ulonglong2*)&h2s[2 * ip][0];
            ulonglong2 h0hi = *(const ulonglong2*)&h2s[2 * ip][4];
            ulonglong2 h1lo = *(const ulonglong2*)&h2s[2 * ip + 1][0];
            ulonglong2 h1hi = *(const ulonglong2*)&h2s[2 * ip + 1][4];
            float2 w = __ldg(&g_w3p[ip * CL + tid]);
            ull wx = pk2(w.x, w.x), wy = pk2(w.y, w.y);
            fma2(acc[0], h0lo.x, wx); fma2(acc[1], h0lo.y, wx);
            fma2(acc[2], h0hi.x, wx); fma2(acc[3], h0hi.y, wx);
            fma2(acc[0], h1lo.x, wy); fma2(acc[1], h1lo.y, wy);
            fma2(acc[2], h1hi.x, wy); fma2(acc[3], h1hi.y, wy);
        }
        float cb = __ldg(&conv3_b[tid]);
        float a[8];
        upk2(acc[0], a[0], a[1]); upk2(acc[1], a[2], a[3]);
        upk2(acc[2], a[4], a[5]); upk2(acc[3], a[6], a[7]);
#pragma unroll
        for (int t = 0; t < 8; t++) y[t] = fmaxf(mx[t] + a[t] + cb, 0.0f);
    }
    float s[3];
    const float4* fw = (const float4*)fc2_w;
#pragma unroll
    for (int k = 0; k < 3; k++) {
        float4 wa = __ldg(&fw[k * 256 + tid * 2]);
        float4 wb = __ldg(&fw[k * 256 + tid * 2 + 1]);
        s[k] = y[0] * wa.x + y[1] * wa.y + y[2] * wa.z + y[3] * wa.w
             + y[4] * wb.x + y[5] * wb.y + y[6] * wb.z + y[7] * wb.w;
    }
#pragma unroll
    for (int k = 0; k < 3; k++)
#pragma unroll
        for (int off = 16; off > 0; off >>= 1)
            s[k] += __shfl_down_sync(0xffffffffu, s[k], off);
    int wid = tid >> 5, lane = tid & 31;
    if (lane == 0) { red[wid][0] = s[0]; red[wid][1] = s[1]; red[wid][2] = s[2]; }
    __syncthreads();
    if (tid < 3)
        out[(size_t)n * 3 + tid] = red[0][tid] + red[1][tid] + red[2][tid] + red[3][tid]
                                 + __ldg(&fc2_b[tid]);
}

// ---------------- launch ----------------
extern "C" void kernel_launch(void* const* d_in, const int* in_sizes, int n_in,
                              void* d_out, int out_size) {
    const float* feature = (const float*)d_in[0];
    const float* lines   = (const float*)d_in[1];
    const float* fc1_w   = (const float*)d_in[2];
    const float* fc1_b   = (const float*)d_in[3];
    float* out = (float*)d_out;

    prep_kernel<<<64, 256>>>(fc1_w,
        (const float*)d_in[4], (const float*)d_in[5], (const float*)d_in[6], (const float*)d_in[7],
        (const float*)d_in[8], (const float*)d_in[9],
        (const float*)d_in[10], (const float*)d_in[11], (const float*)d_in[12], (const float*)d_in[13],
        (const float*)d_in[14], (const float*)d_in[15],
        (const float*)d_in[16], (const float*)d_in[17], (const float*)d_in[18], (const float*)d_in[19],
        (const float*)d_in[20]);
    fc1_tc_kernel<<<(NB * NPIX) / 128, 256>>>(feature, fc1_b);
    line_kernel<<<NB * NL, 128>>>(lines, (const float*)d_in[21],
                                  (const float*)d_in[22], (const float*)d_in[23], out);
}

// round 10
// speedup vs baseline: 1.4050x; 1.4050x over previous
#include <cuda_runtime.h>
#include <cuda_bf16.h>
#include <cuda_fp16.h>
#include <math.h>
#include <stdint.h>

#define NB 2
#define NL 5000
#define HW 256
#define NPIX 65536
#define CIN 256
#define CL 128
#define PL 64
#define EPSB 1e-5f
#define NLC 12
#define RST 132

__device__ float g_xbuf[(size_t)NB * NPIX * CL];
__device__ uint32_t g_fc1ph[(CIN / 2) * CL], g_fc1pl[(CIN / 2) * CL];
__device__ float g_a1[CL], g_b1c[CL];
__device__ float g_b1f[PL], g_b2f[PL];
__device__ uint2 g_c1p[64 * 64];        // conv1 B [kpair][o]
__device__ uint2 g_c2p[3 * 32 * 64];    // conv2 B [dk][kpair][o]
__device__ uint2 g_c3p[32 * 128];       // conv3 B [kpair][o]

__device__ __forceinline__ void sp2(float x, float y, uint32_t& h, uint32_t& l) {
    __nv_bfloat162 hb = __floats2bfloat162_rn(x, y);
    float lx = x - __low2float(hb);
    float ly = y - __high2float(hb);
    __nv_bfloat162 lb = __floats2bfloat162_rn(lx, ly);
    h = *reinterpret_cast<uint32_t*>(&hb);
    l = *reinterpret_cast<uint32_t*>(&lb);
}
__device__ __forceinline__ void mma_bf16(float* d, uint32_t a0, uint32_t a1,
                                         uint32_t a2, uint32_t a3,
                                         uint32_t b0, uint32_t b1) {
    asm volatile(
        "mma.sync.aligned.m16n8k16.row.col.f32.bf16.bf16.f32 "
        "{%0,%1,%2,%3}, {%4,%5,%6,%7}, {%8,%9}, {%0,%1,%2,%3};\n"
        : "+f"(d[0]), "+f"(d[1]), "+f"(d[2]), "+f"(d[3])
        : "r"(a0), "r"(a1), "r"(a2), "r"(a3), "r"(b0), "r"(b1));
}

// ---------------- prep ----------------
__global__ void prep_kernel(const float* __restrict__ fc1_w,
                            const float* __restrict__ bn1_g, const float* __restrict__ bn1_b,
                            const float* __restrict__ bn1_m, const float* __restrict__ bn1_v,
                            const float* __restrict__ conv1_w, const float* __restrict__ conv1_b,
                            const float* __restrict__ bn2_g, const float* __restrict__ bn2_b,
                            const float* __restrict__ bn2_m, const float* __restrict__ bn2_v,
                            const float* __restrict__ conv2_w, const float* __restrict__ conv2_b,
                            const float* __restrict__ bn3_g, const float* __restrict__ bn3_b,
                            const float* __restrict__ bn3_m, const float* __restrict__ bn3_v,
                            const float* __restrict__ conv3_w) {
    int tid = blockIdx.x * blockDim.x + threadIdx.x;
    int nt = gridDim.x * blockDim.x;
    for (int i = tid; i < CL; i += nt) {
        float a = bn1_g[i] * rsqrtf(bn1_v[i] + EPSB);
        g_a1[i] = a;
        g_b1c[i] = bn1_b[i] - bn1_m[i] * a;
    }
    for (int i = tid; i < PL; i += nt) {
        float a2 = bn2_g[i] * rsqrtf(bn2_v[i] + EPSB);
        g_b1f[i] = conv1_b[i] * a2 + bn2_b[i] - bn2_m[i] * a2;
        float a3 = bn3_g[i] * rsqrtf(bn3_v[i] + EPSB);
        g_b2f[i] = conv2_b[i] * a3 + bn3_b[i] - bn3_m[i] * a3;
    }
    for (int i = tid; i < 64 * 64; i += nt) {
        int kp = i >> 6, o = i & 63;
        float a2 = bn2_g[o] * rsqrtf(bn2_v[o] + EPSB);
        uint32_t h, l;
        sp2(conv1_w[o * CL + 2 * kp] * a2, conv1_w[o * CL + 2 * kp + 1] * a2, h, l);
        g_c1p[i] = make_uint2(h, l);
    }
    for (int i = tid; i < 3 * 32 * 64; i += nt) {
        int dk = i / 2048, kp = (i >> 6) & 31, o = i & 63;
        float a3 = bn3_g[o] * rsqrtf(bn3_v[o] + EPSB);
        uint32_t h, l;
        sp2(conv2_w[(o * PL + 2 * kp) * 3 + dk] * a3,
            conv2_w[(o * PL + 2 * kp + 1) * 3 + dk] * a3, h, l);
        g_c2p[i] = make_uint2(h, l);
    }
    for (int i = tid; i < 32 * 128; i += nt) {
        int kp = i >> 7, o = i & 127;
        uint32_t h, l;
        sp2(conv3_w[o * PL + 2 * kp], conv3_w[o * PL + 2 * kp + 1], h, l);
        g_c3p[i] = make_uint2(h, l);
    }
    for (int i = tid; i < (CIN / 2) * CL; i += nt) {
        int kp = i / CL, o = i % CL;
        uint32_t h, l;
        sp2(fc1_w[o * CIN + 2 * kp], fc1_w[o * CIN + 2 * kp + 1], h, l);
        g_fc1ph[i] = h;
        g_fc1pl[i] = l;
    }
}

// ---------------- fc1 (R6 best-measured, verbatim) ----------------
__global__ __launch_bounds__(256) void fc1_tc_kernel(const float* __restrict__ feature,
                                                     const float* __restrict__ fc1_b) {
    __shared__ uint32_t Ah[16][136], Al[16][136];
    __shared__ uint32_t Bh[16][136], Bl[16][136];
    __shared__ float biass[128];

    int tid = threadIdx.x;
    long p0l = (long)blockIdx.x * 128;
    int b = (int)(p0l >> 16);
    int pix0 = (int)(p0l & 65535);
    const float* fb = feature + (size_t)b * CIN * NPIX + pix0;
    if (tid < 128) biass[tid] = fc1_b[tid];

    int wid = tid >> 5, lane = tid & 31;
    int warp_m = wid >> 2, warp_n = wid & 3;
    int grp = lane >> 2, qid = lane & 3;
    int pxb = warp_m * 64, ob = warp_n * 32;

    float acc[4][4][4];
#pragma unroll
    for (int mt = 0; mt < 4; mt++)
#pragma unroll
        for (int nt = 0; nt < 4; nt++)
#pragma unroll
            for (int j = 0; j < 4; j++) acc[mt][nt][j] = 0.0f;

    int p2 = tid >> 4, px0 = (tid & 15) * 8;
    float4 A0a, A0b, A1a, A1b;
    uint4 Wh0, Wh1, Wl0, Wl1;
    {
        const float* fa = fb + (size_t)(2 * p2) * NPIX + px0;
        A0a = *(const float4*)fa;          A0b = *(const float4*)(fa + 4);
        A1a = *(const float4*)(fa + NPIX); A1b = *(const float4*)(fa + NPIX + 4);
        const uint32_t* wh = g_fc1ph + p2 * CL + px0;
        const uint32_t* wl = g_fc1pl + p2 * CL + px0;
        Wh0 = *(const uint4*)wh; Wh1 = *(const uint4*)(wh + 4);
        Wl0 = *(const uint4*)wl; Wl1 = *(const uint4*)(wl + 4);
    }
    for (int ch = 0; ch < 8; ch++) {
        __syncthreads();
        {
            uint4 th, tl;
            sp2(A0a.x, A1a.x, th.x, tl.x); sp2(A0a.y, A1a.y, th.y, tl.y);
            sp2(A0a.z, A1a.z, th.z, tl.z); sp2(A0a.w, A1a.w, th.w, tl.w);
            *(uint4*)&Ah[p2][px0] = th;     *(uint4*)&Al[p2][px0] = tl;
            sp2(A0b.x, A1b.x, th.x, tl.x); sp2(A0b.y, A1b.y, th.y, tl.y);
            sp2(A0b.z, A1b.z, th.z, tl.z); sp2(A0b.w, A1b.w, th.w, tl.w);
            *(uint4*)&Ah[p2][px0 + 4] = th; *(uint4*)&Al[p2][px0 + 4] = tl;
            *(uint4*)&Bh[p2][px0] = Wh0;    *(uint4*)&Bh[p2][px0 + 4] = Wh1;
            *(uint4*)&Bl[p2][px0] = Wl0;    *(uint4*)&Bl[p2][px0 + 4] = Wl1;
        }
        __syncthreads();
        if (ch < 7) {
            int c0 = (ch + 1) * 32;
            const float* fa = fb + (size_t)(c0 + 2 * p2) * NPIX + px0;
            A0a = *(const float4*)fa;          A0b = *(const float4*)(fa + 4);
            A1a = *(const float4*)(fa + NPIX); A1b = *(const float4*)(fa + NPIX + 4);
            const uint32_t* wh = g_fc1ph + ((ch + 1) * 16 + p2) * CL + px0;
            const uint32_t* wl = g_fc1pl + ((ch + 1) * 16 + p2) * CL + px0;
            Wh0 = *(const uint4*)wh; Wh1 = *(const uint4*)(wh + 4);
            Wl0 = *(const uint4*)wl; Wl1 = *(const uint4*)(wl + 4);
        }
#pragma unroll
        for (int ks = 0; ks < 2; ks++) {
            int r0 = ks * 8 + qid;
            const uint32_t *arh = Ah[r0], *arh4 = Ah[r0 + 4];
            const uint32_t *arl = Al[r0], *arl4 = Al[r0 + 4];
            uint32_t ah[4][4], al[4][4];
#pragma unroll
            for (int mt = 0; mt < 4; mt++) {
                int px = pxb + mt * 16 + grp;
                ah[mt][0] = arh[px];  ah[mt][1] = arh[px + 8];
                ah[mt][2] = arh4[px]; ah[mt][3] = arh4[px + 8];
                al[mt][0] = arl[px];  al[mt][1] = arl[px + 8];
                al[mt][2] = arl4[px]; al[mt][3] = arl4[px + 8];
            }
            const uint32_t *brh = Bh[r0], *brh4 = Bh[r0 + 4];
            const uint32_t *brl = Bl[r0], *brl4 = Bl[r0 + 4];
#pragma unroll
            for (int nt = 0; nt < 4; nt++) {
                int oo = ob + nt * 8 + grp;
                uint32_t bh0 = brh[oo], bh1 = brh4[oo];
                uint32_t bl0 = brl[oo], bl1 = brl4[oo];
#pragma unroll
                for (int mt = 0; mt < 4; mt++) {
                    mma_bf16(acc[mt][nt], ah[mt][0], ah[mt][1], ah[mt][2], ah[mt][3], bh0, bh1);
                    mma_bf16(acc[mt][nt], ah[mt][0], ah[mt][1], ah[mt][2], ah[mt][3], bl0, bl1);
                    mma_bf16(acc[mt][nt], al[mt][0], al[mt][1], al[mt][2], al[mt][3], bh0, bh1);
                }
            }
        }
    }
#pragma unroll
    for (int mt = 0; mt < 4; mt++) {
#pragma unroll
        for (int nt = 0; nt < 4; nt++) {
            int px = pix0 + pxb + mt * 16 + grp;
            int oo = ob + nt * 8 + qid * 2;
            float bx = biass[oo], by = biass[oo + 1];
            float2 r0 = make_float2(acc[mt][nt][0] + bx, acc[mt][nt][1] + by);
            float2 r1 = make_float2(acc[mt][nt][2] + bx, acc[mt][nt][3] + by);
            size_t base = ((size_t)b * NPIX + px) * CL + oo;
            *(float2*)&g_xbuf[base] = r0;
            *(float2*)&g_xbuf[base + (size_t)8 * CL] = r1;
        }
    }
}

// ---------------- line: 12 lines/CTA, convs as bf16 MMAs ----------------
#define OFF_H1 67584
#define OFF_H2 101376
#define OFF_XP 135168
#define OFF_SO 167936
#define OFF_SW 174080
#define LINE_SMEM 180480

__global__ __launch_bounds__(256) void line_kernel(const float* __restrict__ lines,
                                                   const float* __restrict__ conv3_b,
                                                   const float* __restrict__ fc2_w,
                                                   const float* __restrict__ fc2_b,
                                                   float* __restrict__ out) {
    extern __shared__ char sm_[];
    uint2* H0 = (uint2*)sm_;
    uint2* H1 = (uint2*)(sm_ + OFF_H1);
    uint2* H2 = (uint2*)(sm_ + OFF_H2);
    __half* XP = (__half*)(sm_ + OFF_XP);
    int4* SO = (int4*)(sm_ + OFF_SO);
    float4* SW = (float4*)(sm_ + OFF_SW);
    float* YB = (float*)sm_;   // aliases H0 (dead after conv1)

    int tid = threadIdx.x;
    int n0 = blockIdx.x * NLC;

    // geometry + zero H1
    for (int i = tid; i < NLC * 32; i += 256) {
        int line = i >> 5, p = i & 31, n = n0 + line;
        if (n < NB * NL) {
            float lam = (float)p * (1.0f / 31.0f);
            const float* lp = lines + (size_t)n * 4;
            float px = lp[0] * lam + lp[2] * (1.0f - lam) - 0.5f;
            float py = lp[1] * lam + lp[3] * (1.0f - lam) - 0.5f;
            float px0 = fminf(fmaxf(floorf(px), 0.0f), 255.0f);
            float py0 = fminf(fmaxf(floorf(py), 0.0f), 255.0f);
            float px1 = fminf(px0 + 1.0f, 255.0f);
            float py1 = fminf(py0 + 1.0f, 255.0f);
            int ix0 = (int)px0, iy0 = (int)py0, ix1 = (int)px1, iy1 = (int)py1;
            SO[i] = make_int4((ix0 * HW + iy0) * CL, (ix1 * HW + iy0) * CL,
                              (ix0 * HW + iy1) * CL, (ix1 * HW + iy1) * CL);
            SW[i] = make_float4((px1 - px) * (py1 - py), (px - px0) * (py1 - py),
                                (px1 - px) * (py - py0), (px - px0) * (py - py0));
        } else {
            SO[i] = make_int4(0, 0, 0, 0);
            SW[i] = make_float4(0.f, 0.f, 0.f, 0.f);
        }
    }
    {
        uint4 z = make_uint4(0, 0, 0, 0);
        uint4* d = (uint4*)(sm_ + OFF_H1);
        for (int i = tid; i < (OFF_H2 - OFF_H1) / 16; i += 256) d[i] = z;
    }
    __syncthreads();

    // sampling + maxpool + BN1 -> H0 planes, xp -> XP
#pragma unroll
    for (int r = 0; r < 3; r++) {
        int task = tid + r * 256;
        int line = task >> 6, cp = task & 63;
        int n = n0 + line;
        int b = (n < NB * NL) ? (n / NL) : (NB - 1);
        const float* xb = g_xbuf + (size_t)b * NPIX * CL + 2 * cp;
        const int4* so = SO + line * 32;
        const float4* sw = SW + line * 32;
        float m0[8], m1[8];
#pragma unroll
        for (int p = 0; p < 32; p++) {
            int4 off = so[p]; float4 w = sw[p];
            float2 c00 = *(const float2*)(xb + off.x);
            float2 c10 = *(const float2*)(xb + off.y);
            float2 c01 = *(const float2*)(xb + off.z);
            float2 c11 = *(const float2*)(xb + off.w);
            float v0 = w.x * c00.x + w.y * c10.x + w.z * c01.x + w.w * c11.x;
            float v1 = w.x * c00.y + w.y * c10.y + w.z * c01.y + w.w * c11.y;
            int t = p >> 2;
            if ((p & 3) == 0) { m0[t] = v0; m1[t] = v1; }
            else { m0[t] = fmaxf(m0[t], v0); m1[t] = fmaxf(m1[t], v1); }
        }
        float a0 = g_a1[2 * cp], a1v = g_a1[2 * cp + 1];
        float b0 = g_b1c[2 * cp], b1v = g_b1c[2 * cp + 1];
#pragma unroll
        for (int t = 0; t < 8; t++) {
            int row = line * 10 + 1 + t;
            *(__half2*)&XP[row * 128 + 2 * cp] = __floats2half2_rn(m0[t], m1[t]);
            uint32_t h, l;
            sp2(fmaxf(m0[t] * a0 + b0, 0.f), fmaxf(m1[t] * a1v + b1v, 0.f), h, l);
            H0[cp * RST + row] = make_uint2(h, l);
        }
    }
    __syncthreads();

    int lane = tid & 31, wid = tid >> 5;
    int grp = lane >> 2, qid = lane & 3;
    int wm = wid >> 2, wn = wid & 3;

    // conv1: M=128, N=64, K=128
    {
        float acc[4][2][4] = {};
        for (int ks = 0; ks < 8; ks++) {
            const uint2* p0 = H0 + (ks * 8 + qid) * RST;
            const uint2* p4 = H0 + (ks * 8 + qid + 4) * RST;
            uint32_t ah[4][4], al[4][4];
#pragma unroll
            for (int mt = 0; mt < 4; mt++) {
                int m = wm * 64 + mt * 16 + grp;
                uint2 e0 = p0[m], e1 = p0[m + 8], e2 = p4[m], e3 = p4[m + 8];
                ah[mt][0] = e0.x; ah[mt][1] = e1.x; ah[mt][2] = e2.x; ah[mt][3] = e3.x;
                al[mt][0] = e0.y; al[mt][1] = e1.y; al[mt][2] = e2.y; al[mt][3] = e3.y;
            }
#pragma unroll
            for (int nt = 0; nt < 2; nt++) {
                int oo = wn * 16 + nt * 8 + grp;
                uint2 b0 = __ldg(&g_c1p[(ks * 8 + qid) * 64 + oo]);
                uint2 b4 = __ldg(&g_c1p[(ks * 8 + qid + 4) * 64 + oo]);
#pragma unroll
                for (int mt = 0; mt < 4; mt++) {
                    mma_bf16(acc[mt][nt], ah[mt][0], ah[mt][1], ah[mt][2], ah[mt][3], b0.x, b4.x);
                    mma_bf16(acc[mt][nt], ah[mt][0], ah[mt][1], ah[mt][2], ah[mt][3], b0.y, b4.y);
                    mma_bf16(acc[mt][nt], al[mt][0], al[mt][1], al[mt][2], al[mt][3], b0.x, b4.x);
                }
            }
        }
#pragma unroll
        for (int mt = 0; mt < 4; mt++)
#pragma unroll
            for (int nt = 0; nt < 2; nt++) {
                int o = wn * 16 + nt * 8 + qid * 2;
                float bx = g_b1f[o], by = g_b1f[o + 1];
#pragma unroll
                for (int half = 0; half < 2; half++) {
                    int row = wm * 64 + mt * 16 + grp + half * 8;
                    if (row >= 1 && row <= 120 && ((row - 1) % 10) < 8) {
                        uint32_t h, l;
                        sp2(fmaxf(acc[mt][nt][half * 2] + bx, 0.f),
                            fmaxf(acc[mt][nt][half * 2 + 1] + by, 0.f), h, l);
                        H1[(o >> 1) * RST + row] = make_uint2(h, l);
                    }
                }
            }
    }
    __syncthreads();

    // conv2: 3 row-shifted passes, K=64
    {
        float acc[4][2][4] = {};
        for (int dk = 0; dk < 3; dk++) {
            for (int ks = 0; ks < 4; ks++) {
                const uint2* p0 = H1 + (ks * 8 + qid) * RST + (dk - 1);
                const uint2* p4 = H1 + (ks * 8 + qid + 4) * RST + (dk - 1);
                uint32_t ah[4][4], al[4][4];
#pragma unroll
                for (int mt = 0; mt < 4; mt++) {
                    int m = wm * 64 + mt * 16 + grp;
                    uint2 e0 = p0[m], e1 = p0[m + 8], e2 = p4[m], e3 = p4[m + 8];
                    ah[mt][0] = e0.x; ah[mt][1] = e1.x; ah[mt][2] = e2.x; ah[mt][3] = e3.x;
                    al[mt][0] = e0.y; al[mt][1] = e1.y; al[mt][2] = e2.y; al[mt][3] = e3.y;
                }
#pragma unroll
                for (int nt = 0; nt < 2; nt++) {
                    int oo = wn * 16 + nt * 8 + grp;
                    uint2 b0 = __ldg(&g_c2p[dk * 2048 + (ks * 8 + qid) * 64 + oo]);
                    uint2 b4 = __ldg(&g_c2p[dk * 2048 + (ks * 8 + qid + 4) * 64 + oo]);
#pragma unroll
                    for (int mt = 0; mt < 4; mt++) {
                        mma_bf16(acc[mt][nt], ah[mt][0], ah[mt][1], ah[mt][2], ah[mt][3], b0.x, b4.x);
                        mma_bf16(acc[mt][nt], ah[mt][0], ah[mt][1], ah[mt][2], ah[mt][3], b0.y, b4.y);
                        mma_bf16(acc[mt][nt], al[mt][0], al[mt][1], al[mt][2], al[mt][3], b0.x, b4.x);
                    }
                }
            }
        }
        __syncthreads();   // H1 reads done before any H2-region writes? H2 separate; sync not needed, kept off
#pragma unroll
        for (int mt = 0; mt < 4; mt++)
#pragma unroll
            for (int nt = 0; nt < 2; nt++) {
                int o = wn * 16 + nt * 8 + qid * 2;
                float bx = g_b2f[o], by = g_b2f[o + 1];
#pragma unroll
                for (int half = 0; half < 2; half++) {
                    int row = wm * 64 + mt * 16 + grp + half * 8;
                    uint32_t h, l;
                    sp2(fmaxf(acc[mt][nt][half * 2] + bx, 0.f),
                        fmaxf(acc[mt][nt][half * 2 + 1] + by, 0.f), h, l);
                    H2[(o >> 1) * RST + row] = make_uint2(h, l);
                }
            }
    }
    __syncthreads();

    // conv3: M=128, N=128, K=64; epilogue: +xp residual, ReLU -> YB
    {
        float acc[4][4][4] = {};
        for (int ks = 0; ks < 4; ks++) {
            const uint2* p0 = H2 + (ks * 8 + qid) * RST;
            const uint2* p4 = H2 + (ks * 8 + qid + 4) * RST;
            uint32_t ah[4][4], al[4][4];
#pragma unroll
            for (int mt = 0; mt < 4; mt++) {
                int m = wm * 64 + mt * 16 + grp;
                uint2 e0 = p0[m], e1 = p0[m + 8], e2 = p4[m], e3 = p4[m + 8];
                ah[mt][0] = e0.x; ah[mt][1] = e1.x; ah[mt][2] = e2.x; ah[mt][3] = e3.x;
                al[mt][0] = e0.y; al[mt][1] = e1.y; al[mt][2] = e2.y; al[mt][3] = e3.y;
            }
#pragma unroll
            for (int nt = 0; nt < 4; nt++) {
                int oo = wn * 32 + nt * 8 + grp;
                uint2 b0 = __ldg(&g_c3p[(ks * 8 + qid) * 128 + oo]);
                uint2 b4 = __ldg(&g_c3p[(ks * 8 + qid + 4) * 128 + oo]);
#pragma unroll
                for (int mt = 0; mt < 4; mt++) {
                    mma_bf16(acc[mt][nt], ah[mt][0], ah[mt][1], ah[mt][2], ah[mt][3], b0.x, b4.x);
                    mma_bf16(acc[mt][nt], ah[mt][0], ah[mt][1], ah[mt][2], ah[mt][3], b0.y, b4.y);
                    mma_bf16(acc[mt][nt], al[mt][0], al[mt][1], al[mt][2], al[mt][3], b0.x, b4.x);
                }
            }
        }
        __syncthreads();   // all H0 fragment reads (none here) / ensure YB alias safe vs other warps' conv1 — already synced
#pragma unroll
        for (int nt = 0; nt < 4; nt++) {
            int oc = wn * 32 + nt * 8 + qid * 2;
            float cbx = __ldg(&conv3_b[oc]), cby = __ldg(&conv3_b[oc + 1]);
#pragma unroll
            for (int mt = 0; mt < 4; mt++)
#pragma unroll
                for (int half = 0; half < 2; half++) {
                    int row = wm * 64 + mt * 16 + grp + half * 8;
                    __half2 xv = *(__half2*)&XP[row * 128 + oc];
                    float y0 = fmaxf(__low2float(xv) + acc[mt][nt][half * 2] + cbx, 0.f);
                    float y1 = fmaxf(__high2float(xv) + acc[mt][nt][half * 2 + 1] + cby, 0.f);
                    *(float2*)&YB[row * 128 + oc] = make_float2(y0, y1);
                }
        }
    }
    __syncthreads();

    // fc2: 16 threads per line
    if (tid < NLC * 16) {
        int line = tid >> 4, sl = tid & 15;
        int n = n0 + line;
        float s0 = 0.f, s1 = 0.f, s2v = 0.f;
#pragma unroll
        for (int j = 0; j < 8; j++) {
            int c = sl * 8 + j;
            float yv[8];
#pragma unroll
            for (int t = 0; t < 8; t++) yv[t] = YB[(line * 10 + 1 + t) * 128 + c];
            int f = c * 8;
#pragma unroll
            for (int k = 0; k < 3; k++) {
                const float4* fw = (const float4*)(fc2_w + k * 1024 + f);
                float4 wa = __ldg(fw), wb = __ldg(fw + 1);
                float d = yv[0] * wa.x + yv[1] * wa.y + yv[2] * wa.z + yv[3] * wa.w
                        + yv[4] * wb.x + yv[5] * wb.y + yv[6] * wb.z + yv[7] * wb.w;
                if (k == 0) s0 += d; else if (k == 1) s1 += d; else s2v += d;
            }
        }
#pragma unroll
        for (int off = 8; off > 0; off >>= 1) {
            s0 += __shfl_down_sync(0xffffffffu, s0, off, 16);
            s1 += __shfl_down_sync(0xffffffffu, s1, off, 16);
            s2v += __shfl_down_sync(0xffffffffu, s2v, off, 16);
        }
        if (sl == 0 && n < NB * NL) {
            out[(size_t)n * 3 + 0] = s0 + __ldg(&fc2_b[0]);
            out[(size_t)n * 3 + 1] = s1 + __ldg(&fc2_b[1]);
            out[(size_t)n * 3 + 2] = s2v + __ldg(&fc2_b[2]);
        }
    }
}

// ---------------- launch ----------------
extern "C" void kernel_launch(void* const* d_in, const int* in_sizes, int n_in,
                              void* d_out, int out_size) {
    const float* feature = (const float*)d_in[0];
    const float* lines = (const float*)d_in[1];
    float* out = (float*)d_out;

    prep_kernel<<<64, 256>>>((const float*)d_in[2],
        (const float*)d_in[4], (const float*)d_in[5], (const float*)d_in[6], (const float*)d_in[7],
        (const float*)d_in[8], (const float*)d_in[9],
        (const float*)d_in[10], (const float*)d_in[11], (const float*)d_in[12], (const float*)d_in[13],
        (const float*)d_in[14], (const float*)d_in[15],
        (const float*)d_in[16], (const float*)d_in[17], (const float*)d_in[18], (const float*)d_in[19],
        (const float*)d_in[20]);
    fc1_tc_kernel<<<(NB * NPIX) / 128, 256>>>(feature, (const float*)d_in[3]);
    cudaFuncSetAttribute(line_kernel, cudaFuncAttributeMaxDynamicSharedMemorySize, LINE_SMEM);
    int nblk = (NB * NL + NLC - 1) / NLC;
    line_kernel<<<nblk, 256, LINE_SMEM>>>(lines, (const float*)d_in[21],
                                          (const float*)d_in[22], (const float*)d_in[23], out);
}

// round 12
// speedup vs baseline: 1.4965x; 1.0652x over previous
#include <cuda_runtime.h>
#include <cuda_bf16.h>
#include <cuda_fp16.h>
#include <math.h>
#include <stdint.h>

#define NB 2
#define NL 5000
#define HW 256
#define NPIX 65536
#define CIN 256
#define CL 128
#define PL 64
#define EPSB 1e-5f
#define NLC 12
#define RST 132

__device__ float g_xbuf[(size_t)NB * NPIX * CL];
__device__ uint32_t g_fc1ph[(CIN / 2) * CL], g_fc1pl[(CIN / 2) * CL];  // fp16x2 hi/lo
__device__ float g_a1[CL], g_b1c[CL];
__device__ float g_b1f[PL], g_b2f[PL];
__device__ uint2 g_c1p[64 * 64];        // conv1 B [kpair][o] (bf16 hi,lo)
__device__ uint2 g_c2p[3 * 32 * 64];    // conv2 B [dk][kpair][o]
__device__ uint2 g_c3p[32 * 128];       // conv3 B [kpair][o]

// bf16 2-term split of a pair
__device__ __forceinline__ void sp2(float x, float y, uint32_t& h, uint32_t& l) {
    __nv_bfloat162 hb = __floats2bfloat162_rn(x, y);
    float lx = x - __low2float(hb);
    float ly = y - __high2float(hb);
    __nv_bfloat162 lb = __floats2bfloat162_rn(lx, ly);
    h = *reinterpret_cast<uint32_t*>(&hb);
    l = *reinterpret_cast<uint32_t*>(&lb);
}
// fp16 2-term split of a pair
__device__ __forceinline__ void sp2h(float x, float y, uint32_t& h, uint32_t& l) {
    __half2 hb = __floats2half2_rn(x, y);
    float lx = x - __low2float(hb);
    float ly = y - __high2float(hb);
    __half2 lb = __floats2half2_rn(lx, ly);
    h = *reinterpret_cast<uint32_t*>(&hb);
    l = *reinterpret_cast<uint32_t*>(&lb);
}
__device__ __forceinline__ void mma_bf16(float* d, uint32_t a0, uint32_t a1,
                                         uint32_t a2, uint32_t a3,
                                         uint32_t b0, uint32_t b1) {
    asm volatile(
        "mma.sync.aligned.m16n8k16.row.col.f32.bf16.bf16.f32 "
        "{%0,%1,%2,%3}, {%4,%5,%6,%7}, {%8,%9}, {%0,%1,%2,%3};\n"
        : "+f"(d[0]), "+f"(d[1]), "+f"(d[2]), "+f"(d[3])
        : "r"(a0), "r"(a1), "r"(a2), "r"(a3), "r"(b0), "r"(b1));
}
__device__ __forceinline__ void mma_fp16(float* d, uint32_t a0, uint32_t a1,
                                         uint32_t a2, uint32_t a3,
                                         uint32_t b0, uint32_t b1) {
    asm volatile(
        "mma.sync.aligned.m16n8k16.row.col.f32.f16.f16.f32 "
        "{%0,%1,%2,%3}, {%4,%5,%6,%7}, {%8,%9}, {%0,%1,%2,%3};\n"
        : "+f"(d[0]), "+f"(d[1]), "+f"(d[2]), "+f"(d[3])
        : "r"(a0), "r"(a1), "r"(a2), "r"(a3), "r"(b0), "r"(b1));
}

// ---------------- prep ----------------
__global__ void prep_kernel(const float* __restrict__ fc1_w,
                            const float* __restrict__ bn1_g, const float* __restrict__ bn1_b,
                            const float* __restrict__ bn1_m, const float* __restrict__ bn1_v,
                            const float* __restrict__ conv1_w, const float* __restrict__ conv1_b,
                            const float* __restrict__ bn2_g, const float* __restrict__ bn2_b,
                            const float* __restrict__ bn2_m, const float* __restrict__ bn2_v,
                            const float* __restrict__ conv2_w, const float* __restrict__ conv2_b,
                            const float* __restrict__ bn3_g, const float* __restrict__ bn3_b,
                            const float* __restrict__ bn3_m, const float* __restrict__ bn3_v,
                            const float* __restrict__ conv3_w) {
    int tid = blockIdx.x * blockDim.x + threadIdx.x;
    int nt = gridDim.x * blockDim.x;
    for (int i = tid; i < CL; i += nt) {
        float a = bn1_g[i] * rsqrtf(bn1_v[i] + EPSB);
        g_a1[i] = a;
        g_b1c[i] = bn1_b[i] - bn1_m[i] * a;
    }
    for (int i = tid; i < PL; i += nt) {
        float a2 = bn2_g[i] * rsqrtf(bn2_v[i] + EPSB);
        g_b1f[i] = conv1_b[i] * a2 + bn2_b[i] - bn2_m[i] * a2;
        float a3 = bn3_g[i] * rsqrtf(bn3_v[i] + EPSB);
        g_b2f[i] = conv2_b[i] * a3 + bn3_b[i] - bn3_m[i] * a3;
    }
    for (int i = tid; i < 64 * 64; i += nt) {
        int kp = i >> 6, o = i & 63;
        float a2 = bn2_g[o] * rsqrtf(bn2_v[o] + EPSB);
        uint32_t h, l;
        sp2(conv1_w[o * CL + 2 * kp] * a2, conv1_w[o * CL + 2 * kp + 1] * a2, h, l);
        g_c1p[i] = make_uint2(h, l);
    }
    for (int i = tid; i < 3 * 32 * 64; i += nt) {
        int dk = i / 2048, kp = (i >> 6) & 31, o = i & 63;
        float a3 = bn3_g[o] * rsqrtf(bn3_v[o] + EPSB);
        uint32_t h, l;
        sp2(conv2_w[(o * PL + 2 * kp) * 3 + dk] * a3,
            conv2_w[(o * PL + 2 * kp + 1) * 3 + dk] * a3, h, l);
        g_c2p[i] = make_uint2(h, l);
    }
    for (int i = tid; i < 32 * 128; i += nt) {
        int kp = i >> 7, o = i & 127;
        uint32_t h, l;
        sp2(conv3_w[o * PL + 2 * kp], conv3_w[o * PL + 2 * kp + 1], h, l);
        g_c3p[i] = make_uint2(h, l);
    }
    // fc1 weights: fp16 2-term split, [chunk*16+kpair][o]
    for (int i = tid; i < (CIN / 2) * CL; i += nt) {
        int kp = i / CL, o = i % CL;
        uint32_t h, l;
        sp2h(fc1_w[o * CIN + 2 * kp], fc1_w[o * CIN + 2 * kp + 1], h, l);
        g_fc1ph[i] = h;
        g_fc1pl[i] = l;
    }
}

// ---------------- fc1: mma.sync fp16, A unsplit + B 2-term split (2 products) ----------------
__global__ __launch_bounds__(256) void fc1_tc_kernel(const float* __restrict__ feature,
                                                     const float* __restrict__ fc1_b) {
    __shared__ uint32_t Ax[16][136];               // [kpair][px] fp16x2
    __shared__ uint32_t Bh[16][136], Bl[16][136];  // [kpair][o] fp16x2 hi/lo
    __shared__ float biass[128];

    int tid = threadIdx.x;
    long p0l = (long)blockIdx.x * 128;
    int b = (int)(p0l >> 16);
    int pix0 = (int)(p0l & 65535);
    const float* fb = feature + (size_t)b * CIN * NPIX + pix0;
    if (tid < 128) biass[tid] = fc1_b[tid];

    int wid = tid >> 5, lane = tid & 31;
    int warp_m = wid >> 2, warp_n = wid & 3;
    int grp = lane >> 2, qid = lane & 3;
    int pxb = warp_m * 64, ob = warp_n * 32;

    float acc[4][4][4];
#pragma unroll
    for (int mt = 0; mt < 4; mt++)
#pragma unroll
        for (int nt = 0; nt < 4; nt++)
#pragma unroll
            for (int j = 0; j < 4; j++) acc[mt][nt][j] = 0.0f;

    int p2 = tid >> 4, px0 = (tid & 15) * 8;
    float4 A0a, A0b, A1a, A1b;
    uint4 Wh0, Wh1, Wl0, Wl1;
    {
        const float* fa = fb + (size_t)(2 * p2) * NPIX + px0;
        A0a = *(const float4*)fa;          A0b = *(const float4*)(fa + 4);
        A1a = *(const float4*)(fa + NPIX); A1b = *(const float4*)(fa + NPIX + 4);
        const uint32_t* wh = g_fc1ph + p2 * CL + px0;
        const uint32_t* wl = g_fc1pl + p2 * CL + px0;
        Wh0 = *(const uint4*)wh; Wh1 = *(const uint4*)(wh + 4);
        Wl0 = *(const uint4*)wl; Wl1 = *(const uint4*)(wl + 4);
    }
    for (int ch = 0; ch < 8; ch++) {
        __syncthreads();
        {
            // A: fp16x2 over adjacent-k pair (rn, unsplit)
            uint4 t;
            __half2 h;
            h = __floats2half2_rn(A0a.x, A1a.x); t.x = *(uint32_t*)&h;
            h = __floats2half2_rn(A0a.y, A1a.y); t.y = *(uint32_t*)&h;
            h = __floats2half2_rn(A0a.z, A1a.z); t.z = *(uint32_t*)&h;
            h = __floats2half2_rn(A0a.w, A1a.w); t.w = *(uint32_t*)&h;
            *(uint4*)&Ax[p2][px0] = t;
            h = __floats2half2_rn(A0b.x, A1b.x); t.x = *(uint32_t*)&h;
            h = __floats2half2_rn(A0b.y, A1b.y); t.y = *(uint32_t*)&h;
            h = __floats2half2_rn(A0b.z, A1b.z); t.z = *(uint32_t*)&h;
            h = __floats2half2_rn(A0b.w, A1b.w); t.w = *(uint32_t*)&h;
            *(uint4*)&Ax[p2][px0 + 4] = t;
            *(uint4*)&Bh[p2][px0] = Wh0;    *(uint4*)&Bh[p2][px0 + 4] = Wh1;
            *(uint4*)&Bl[p2][px0] = Wl0;    *(uint4*)&Bl[p2][px0 + 4] = Wl1;
        }
        __syncthreads();
        if (ch < 7) {
            int c0 = (ch + 1) * 32;
            const float* fa = fb + (size_t)(c0 + 2 * p2) * NPIX + px0;
            A0a = *(const float4*)fa;          A0b = *(const float4*)(fa + 4);
            A1a = *(const float4*)(fa + NPIX); A1b = *(const float4*)(fa + NPIX + 4);
            const uint32_t* wh = g_fc1ph + ((ch + 1) * 16 + p2) * CL + px0;
            const uint32_t* wl = g_fc1pl + ((ch + 1) * 16 + p2) * CL + px0;
            Wh0 = *(const uint4*)wh; Wh1 = *(const uint4*)(wh + 4);
            Wl0 = *(const uint4*)wl; Wl1 = *(const uint4*)(wl + 4);
        }
#pragma unroll
        for (int ks = 0; ks < 2; ks++) {
            int r0 = ks * 8 + qid;
            const uint32_t *ar = Ax[r0], *ar4 = Ax[r0 + 4];
            uint32_t ah[4][4];
#pragma unroll
            for (int mt = 0; mt < 4; mt++) {
                int px = pxb + mt * 16 + grp;
                ah[mt][0] = ar[px];  ah[mt][1] = ar[px + 8];
                ah[mt][2] = ar4[px]; ah[mt][3] = ar4[px + 8];
            }
            const uint32_t *brh = Bh[r0], *brh4 = Bh[r0 + 4];
            const uint32_t *brl = Bl[r0], *brl4 = Bl[r0 + 4];
#pragma unroll
            for (int nt = 0; nt < 4; nt++) {
                int oo = ob + nt * 8 + grp;
                uint32_t bh0 = brh[oo], bh1 = brh4[oo];
                uint32_t bl0 = brl[oo], bl1 = brl4[oo];
#pragma unroll
                for (int mt = 0; mt < 4; mt++) {
                    mma_fp16(acc[mt][nt], ah[mt][0], ah[mt][1], ah[mt][2], ah[mt][3], bh0, bh1);
                    mma_fp16(acc[mt][nt], ah[mt][0], ah[mt][1], ah[mt][2], ah[mt][3], bl0, bl1);
                }
            }
        }
    }
#pragma unroll
    for (int mt = 0; mt < 4; mt++) {
#pragma unroll
        for (int nt = 0; nt < 4; nt++) {
            int px = pix0 + pxb + mt * 16 + grp;
            int oo = ob + nt * 8 + qid * 2;
            float bx = biass[oo], by = biass[oo + 1];
            float2 r0 = make_float2(acc[mt][nt][0] + bx, acc[mt][nt][1] + by);
            float2 r1 = make_float2(acc[mt][nt][2] + bx, acc[mt][nt][3] + by);
            size_t base = ((size_t)b * NPIX + px) * CL + oo;
            *(float2*)&g_xbuf[base] = r0;
            *(float2*)&g_xbuf[base + (size_t)8 * CL] = r1;
        }
    }
}

// ---------------- line: 12 lines/CTA, convs as bf16 MMAs (R10 verbatim) ----------------
#define OFF_H1 67584
#define OFF_H2 101376
#define OFF_XP 135168
#define OFF_SO 167936
#define OFF_SW 174080
#define LINE_SMEM 180480

__global__ __launch_bounds__(256) void line_kernel(const float* __restrict__ lines,
                                                   const float* __restrict__ conv3_b,
                                                   const float* __restrict__ fc2_w,
                                                   const float* __restrict__ fc2_b,
                                                   float* __restrict__ out) {
    extern __shared__ char sm_[];
    uint2* H0 = (uint2*)sm_;
    uint2* H1 = (uint2*)(sm_ + OFF_H1);
    uint2* H2 = (uint2*)(sm_ + OFF_H2);
    __half* XP = (__half*)(sm_ + OFF_XP);
    int4* SO = (int4*)(sm_ + OFF_SO);
    float4* SW = (float4*)(sm_ + OFF_SW);
    float* YB = (float*)sm_;

    int tid = threadIdx.x;
    int n0 = blockIdx.x * NLC;

    for (int i = tid; i < NLC * 32; i += 256) {
        int line = i >> 5, p = i & 31, n = n0 + line;
        if (n < NB * NL) {
            float lam = (float)p * (1.0f / 31.0f);
            const float* lp = lines + (size_t)n * 4;
            float px = lp[0] * lam + lp[2] * (1.0f - lam) - 0.5f;
            float py = lp[1] * lam + lp[3] * (1.0f - lam) - 0.5f;
            float px0 = fminf(fmaxf(floorf(px), 0.0f), 255.0f);
            float py0 = fminf(fmaxf(floorf(py), 0.0f), 255.0f);
            float px1 = fminf(px0 + 1.0f, 255.0f);
            float py1 = fminf(py0 + 1.0f, 255.0f);
            int ix0 = (int)px0, iy0 = (int)py0, ix1 = (int)px1, iy1 = (int)py1;
            SO[i] = make_int4((ix0 * HW + iy0) * CL, (ix1 * HW + iy0) * CL,
                              (ix0 * HW + iy1) * CL, (ix1 * HW + iy1) * CL);
            SW[i] = make_float4((px1 - px) * (py1 - py), (px - px0) * (py1 - py),
                                (px1 - px) * (py - py0), (px - px0) * (py - py0));
        } else {
            SO[i] = make_int4(0, 0, 0, 0);
            SW[i] = make_float4(0.f, 0.f, 0.f, 0.f);
        }
    }
    {
        uint4 z = make_uint4(0, 0, 0, 0);
        uint4* d = (uint4*)(sm_ + OFF_H1);
        for (int i = tid; i < (OFF_H2 - OFF_H1) / 16; i += 256) d[i] = z;
    }
    __syncthreads();

#pragma unroll
    for (int r = 0; r < 3; r++) {
        int task = tid + r * 256;
        int line = task >> 6, cp = task & 63;
        int n = n0 + line;
        int b = (n < NB * NL) ? (n / NL) : (NB - 1);
        const float* xb = g_xbuf + (size_t)b * NPIX * CL + 2 * cp;
        const int4* so = SO + line * 32;
        const float4* sw = SW + line * 32;
        float m0[8], m1[8];
#pragma unroll
        for (int p = 0; p < 32; p++) {
            int4 off = so[p]; float4 w = sw[p];
            float2 c00 = *(const float2*)(xb + off.x);
            float2 c10 = *(const float2*)(xb + off.y);
            float2 c01 = *(const float2*)(xb + off.z);
            float2 c11 = *(const float2*)(xb + off.w);
            float v0 = w.x * c00.x + w.y * c10.x + w.z * c01.x + w.w * c11.x;
            float v1 = w.x * c00.y + w.y * c10.y + w.z * c01.y + w.w * c11.y;
            int t = p >> 2;
            if ((p & 3) == 0) { m0[t] = v0; m1[t] = v1; }
            else { m0[t] = fmaxf(m0[t], v0); m1[t] = fmaxf(m1[t], v1); }
        }
        float a0 = g_a1[2 * cp], a1v = g_a1[2 * cp + 1];
        float b0 = g_b1c[2 * cp], b1v = g_b1c[2 * cp + 1];
#pragma unroll
        for (int t = 0; t < 8; t++) {
            int row = line * 10 + 1 + t;
            *(__half2*)&XP[row * 128 + 2 * cp] = __floats2half2_rn(m0[t], m1[t]);
            uint32_t h, l;
            sp2(fmaxf(m0[t] * a0 + b0, 0.f), fmaxf(m1[t] * a1v + b1v, 0.f), h, l);
            H0[cp * RST + row] = make_uint2(h, l);
        }
    }
    __syncthreads();

    int lane = tid & 31, wid = tid >> 5;
    int grp = lane >> 2, qid = lane & 3;
    int wm = wid >> 2, wn = wid & 3;

    // conv1
    {
        float acc[4][2][4] = {};
        for (int ks = 0; ks < 8; ks++) {
            const uint2* p0 = H0 + (ks * 8 + qid) * RST;
            const uint2* p4 = H0 + (ks * 8 + qid + 4) * RST;
            uint32_t ah[4][4], al[4][4];
#pragma unroll
            for (int mt = 0; mt < 4; mt++) {
                int m = wm * 64 + mt * 16 + grp;
                uint2 e0 = p0[m], e1 = p0[m + 8], e2 = p4[m], e3 = p4[m + 8];
                ah[mt][0] = e0.x; ah[mt][1] = e1.x; ah[mt][2] = e2.x; ah[mt][3] = e3.x;
                al[mt][0] = e0.y; al[mt][1] = e1.y; al[mt][2] = e2.y; al[mt][3] = e3.y;
            }
#pragma unroll
            for (int nt = 0; nt < 2; nt++) {
                int oo = wn * 16 + nt * 8 + grp;
                uint2 b0 = __ldg(&g_c1p[(ks * 8 + qid) * 64 + oo]);
                uint2 b4 = __ldg(&g_c1p[(ks * 8 + qid + 4) * 64 + oo]);
#pragma unroll
                for (int mt = 0; mt < 4; mt++) {
                    mma_bf16(acc[mt][nt], ah[mt][0], ah[mt][1], ah[mt][2], ah[mt][3], b0.x, b4.x);
                    mma_bf16(acc[mt][nt], ah[mt][0], ah[mt][1], ah[mt][2], ah[mt][3], b0.y, b4.y);
                    mma_bf16(acc[mt][nt], al[mt][0], al[mt][1], al[mt][2], al[mt][3], b0.x, b4.x);
                }
            }
        }
#pragma unroll
        for (int mt = 0; mt < 4; mt++)
#pragma unroll
            for (int nt = 0; nt < 2; nt++) {
                int o = wn * 16 + nt * 8 + qid * 2;
                float bx = g_b1f[o], by = g_b1f[o + 1];
#pragma unroll
                for (int half = 0; half < 2; half++) {
                    int row = wm * 64 + mt * 16 + grp + half * 8;
                    if (row >= 1 && row <= 120 && ((row - 1) % 10) < 8) {
                        uint32_t h, l;
                        sp2(fmaxf(acc[mt][nt][half * 2] + bx, 0.f),
                            fmaxf(acc[mt][nt][half * 2 + 1] + by, 0.f), h, l);
                        H1[(o >> 1) * RST + row] = make_uint2(h, l);
                    }
                }
            }
    }
    __syncthreads();

    // conv2
    {
        float acc[4][2][4] = {};
        for (int dk = 0; dk < 3; dk++) {
            for (int ks = 0; ks < 4; ks++) {
                const uint2* p0 = H1 + (ks * 8 + qid) * RST + (dk - 1);
                const uint2* p4 = H1 + (ks * 8 + qid + 4) * RST + (dk - 1);
                uint32_t ah[4][4], al[4][4];
#pragma unroll
                for (int mt = 0; mt < 4; mt++) {
                    int m = wm * 64 + mt * 16 + grp;
                    uint2 e0 = p0[m], e1 = p0[m + 8], e2 = p4[m], e3 = p4[m + 8];
                    ah[mt][0] = e0.x; ah[mt][1] = e1.x; ah[mt][2] = e2.x; ah[mt][3] = e3.x;
                    al[mt][0] = e0.y; al[mt][1] = e1.y; al[mt][2] = e2.y; al[mt][3] = e3.y;
                }
#pragma unroll
                for (int nt = 0; nt < 2; nt++) {
                    int oo = wn * 16 + nt * 8 + grp;
                    uint2 b0 = __ldg(&g_c2p[dk * 2048 + (ks * 8 + qid) * 64 + oo]);
                    uint2 b4 = __ldg(&g_c2p[dk * 2048 + (ks * 8 + qid + 4) * 64 + oo]);
#pragma unroll
                    for (int mt = 0; mt < 4; mt++) {
                        mma_bf16(acc[mt][nt], ah[mt][0], ah[mt][1], ah[mt][2], ah[mt][3], b0.x, b4.x);
                        mma_bf16(acc[mt][nt], ah[mt][0], ah[mt][1], ah[mt][2], ah[mt][3], b0.y, b4.y);
                        mma_bf16(acc[mt][nt], al[mt][0], al[mt][1], al[mt][2], al[mt][3], b0.x, b4.x);
                    }
                }
            }
        }
        __syncthreads();
#pragma unroll
        for (int mt = 0; mt < 4; mt++)
#pragma unroll
            for (int nt = 0; nt < 2; nt++) {
                int o = wn * 16 + nt * 8 + qid * 2;
                float bx = g_b2f[o], by = g_b2f[o + 1];
#pragma unroll
                for (int half = 0; half < 2; half++) {
                    int row = wm * 64 + mt * 16 + grp + half * 8;
                    uint32_t h, l;
                    sp2(fmaxf(acc[mt][nt][half * 2] + bx, 0.f),
                        fmaxf(acc[mt][nt][half * 2 + 1] + by, 0.f), h, l);
                    H2[(o >> 1) * RST + row] = make_uint2(h, l);
                }
            }
    }
    __syncthreads();

    // conv3 + residual + ReLU
    {
        float acc[4][4][4] = {};
        for (int ks = 0; ks < 4; ks++) {
            const uint2* p0 = H2 + (ks * 8 + qid) * RST;
            const uint2* p4 = H2 + (ks * 8 + qid + 4) * RST;
            uint32_t ah[4][4], al[4][4];
#pragma unroll
            for (int mt = 0; mt < 4; mt++) {
                int m = wm * 64 + mt * 16 + grp;
                uint2 e0 = p0[m], e1 = p0[m + 8], e2 = p4[m], e3 = p4[m + 8];
                ah[mt][0] = e0.x; ah[mt][1] = e1.x; ah[mt][2] = e2.x; ah[mt][3] = e3.x;
                al[mt][0] = e0.y; al[mt][1] = e1.y; al[mt][2] = e2.y; al[mt][3] = e3.y;
            }
#pragma unroll
            for (int nt = 0; nt < 4; nt++) {
                int oo = wn * 32 + nt * 8 + grp;
                uint2 b0 = __ldg(&g_c3p[(ks * 8 + qid) * 128 + oo]);
                uint2 b4 = __ldg(&g_c3p[(ks * 8 + qid + 4) * 128 + oo]);
#pragma unroll
                for (int mt = 0; mt < 4; mt++) {
                    mma_bf16(acc[mt][nt], ah[mt][0], ah[mt][1], ah[mt][2], ah[mt][3], b0.x, b4.x);
                    mma_bf16(acc[mt][nt], ah[mt][0], ah[mt][1], ah[mt][2], ah[mt][3], b0.y, b4.y);
                    mma_bf16(acc[mt][nt], al[mt][0], al[mt][1], al[mt][2], al[mt][3], b0.x, b4.x);
                }
            }
        }
        __syncthreads();
#pragma unroll
        for (int nt = 0; nt < 4; nt++) {
            int oc = wn * 32 + nt * 8 + qid * 2;
            float cbx = __ldg(&conv3_b[oc]), cby = __ldg(&conv3_b[oc + 1]);
#pragma unroll
            for (int mt = 0; mt < 4; mt++)
#pragma unroll
                for (int half = 0; half < 2; half++) {
                    int row = wm * 64 + mt * 16 + grp + half * 8;
                    __half2 xv = *(__half2*)&XP[row * 128 + oc];
                    float y0 = fmaxf(__low2float(xv) + acc[mt][nt][half * 2] + cbx, 0.f);
                    float y1 = fmaxf(__high2float(xv) + acc[mt][nt][half * 2 + 1] + cby, 0.f);
                    *(float2*)&YB[row * 128 + oc] = make_float2(y0, y1);
                }
        }
    }
    __syncthreads();

    // fc2
    if (tid < NLC * 16) {
        int line = tid >> 4, sl = tid & 15;
        int n = n0 + line;
        float s0 = 0.f, s1 = 0.f, s2v = 0.f;
#pragma unroll
        for (int j = 0; j < 8; j++) {
            int c = sl * 8 + j;
            float yv[8];
#pragma unroll
            for (int t = 0; t < 8; t++) yv[t] = YB[(line * 10 + 1 + t) * 128 + c];
            int f = c * 8;
#pragma unroll
            for (int k = 0; k < 3; k++) {
                const float4* fw = (const float4*)(fc2_w + k * 1024 + f);
                float4 wa = __ldg(fw), wb = __ldg(fw + 1);
                float d = yv[0] * wa.x + yv[1] * wa.y + yv[2] * wa.z + yv[3] * wa.w
                        + yv[4] * wb.x + yv[5] * wb.y + yv[6] * wb.z + yv[7] * wb.w;
                if (k == 0) s0 += d; else if (k == 1) s1 += d; else s2v += d;
            }
        }
#pragma unroll
        for (int off = 8; off > 0; off >>= 1) {
            s0 += __shfl_down_sync(0xffffffffu, s0, off, 16);
            s1 += __shfl_down_sync(0xffffffffu, s1, off, 16);
            s2v += __shfl_down_sync(0xffffffffu, s2v, off, 16);
        }
        if (sl == 0 && n < NB * NL) {
            out[(size_t)n * 3 + 0] = s0 + __ldg(&fc2_b[0]);
            out[(size_t)n * 3 + 1] = s1 + __ldg(&fc2_b[1]);
            out[(size_t)n * 3 + 2] = s2v + __ldg(&fc2_b[2]);
        }
    }
}

// ---------------- launch ----------------
extern "C" void kernel_launch(void* const* d_in, const int* in_sizes, int n_in,
                              void* d_out, int out_size) {
    const float* feature = (const float*)d_in[0];
    const float* lines = (const float*)d_in[1];
    float* out = (float*)d_out;

    prep_kernel<<<64, 256>>>((const float*)d_in[2],
        (const float*)d_in[4], (const float*)d_in[5], (const float*)d_in[6], (const float*)d_in[7],
        (const float*)d_in[8], (const float*)d_in[9],
        (const float*)d_in[10], (const float*)d_in[11], (const float*)d_in[12], (const float*)d_in[13],
        (const float*)d_in[14], (const float*)d_in[15],
        (const float*)d_in[16], (const float*)d_in[17], (const float*)d_in[18], (const float*)d_in[19],
        (const float*)d_in[20]);
    fc1_tc_kernel<<<(NB * NPIX) / 128, 256>>>(feature, (const float*)d_in[3]);
    cudaFuncSetAttribute(line_kernel, cudaFuncAttributeMaxDynamicSharedMemorySize, LINE_SMEM);
    int nblk = (NB * NL + NLC - 1) / NLC;
    line_kernel<<<nblk, 256, LINE_SMEM>>>(lines, (const float*)d_in[21],
                                          (const float*)d_in[22], (const float*)d_in[23], out);
}

// round 13
// speedup vs baseline: 1.7221x; 1.1507x over previous
#include <cuda_runtime.h>
#include <cuda_bf16.h>
#include <cuda_fp16.h>
#include <math.h>
#include <stdint.h>

#define NB 2
#define NL 5000
#define HW 256
#define NPIX 65536
#define CIN 256
#define CL 128
#define PL 64
#define EPSB 1e-5f
#define NLC 12
#define RST 136

__device__ float g_xbuf[(size_t)NB * NPIX * CL];
__device__ uint32_t g_fc1ph[(CIN / 2) * CL], g_fc1pl[(CIN / 2) * CL];  // fp16x2 hi/lo
__device__ float g_a1[CL], g_b1c[CL];
__device__ float g_b1f[PL], g_b2f[PL];
__device__ uint2 g_c1p[64 * 64];        // conv1 B [kpair][o] (fp16 hi,lo)
__device__ uint2 g_c2p[3 * 32 * 64];    // conv2 B [dk][kpair][o]
__device__ uint2 g_c3p[32 * 128];       // conv3 B [kpair][o]

// fp16 2-term split of a pair
__device__ __forceinline__ void sp2h(float x, float y, uint32_t& h, uint32_t& l) {
    __half2 hb = __floats2half2_rn(x, y);
    float lx = x - __low2float(hb);
    float ly = y - __high2float(hb);
    __half2 lb = __floats2half2_rn(lx, ly);
    h = *reinterpret_cast<uint32_t*>(&hb);
    l = *reinterpret_cast<uint32_t*>(&lb);
}
__device__ __forceinline__ uint32_t pkh(float x, float y) {
    __half2 h = __floats2half2_rn(x, y);
    return *reinterpret_cast<uint32_t*>(&h);
}
__device__ __forceinline__ void mma_fp16(float* d, uint32_t a0, uint32_t a1,
                                         uint32_t a2, uint32_t a3,
                                         uint32_t b0, uint32_t b1) {
    asm volatile(
        "mma.sync.aligned.m16n8k16.row.col.f32.f16.f16.f32 "
        "{%0,%1,%2,%3}, {%4,%5,%6,%7}, {%8,%9}, {%0,%1,%2,%3};\n"
        : "+f"(d[0]), "+f"(d[1]), "+f"(d[2]), "+f"(d[3])
        : "r"(a0), "r"(a1), "r"(a2), "r"(a3), "r"(b0), "r"(b1));
}

// ---------------- prep ----------------
__global__ void prep_kernel(const float* __restrict__ fc1_w,
                            const float* __restrict__ bn1_g, const float* __restrict__ bn1_b,
                            const float* __restrict__ bn1_m, const float* __restrict__ bn1_v,
                            const float* __restrict__ conv1_w, const float* __restrict__ conv1_b,
                            const float* __restrict__ bn2_g, const float* __restrict__ bn2_b,
                            const float* __restrict__ bn2_m, const float* __restrict__ bn2_v,
                            const float* __restrict__ conv2_w, const float* __restrict__ conv2_b,
                            const float* __restrict__ bn3_g, const float* __restrict__ bn3_b,
                            const float* __restrict__ bn3_m, const float* __restrict__ bn3_v,
                            const float* __restrict__ conv3_w) {
    int tid = blockIdx.x * blockDim.x + threadIdx.x;
    int nt = gridDim.x * blockDim.x;
    for (int i = tid; i < CL; i += nt) {
        float a = bn1_g[i] * rsqrtf(bn1_v[i] + EPSB);
        g_a1[i] = a;
        g_b1c[i] = bn1_b[i] - bn1_m[i] * a;
    }
    for (int i = tid; i < PL; i += nt) {
        float a2 = bn2_g[i] * rsqrtf(bn2_v[i] + EPSB);
        g_b1f[i] = conv1_b[i] * a2 + bn2_b[i] - bn2_m[i] * a2;
        float a3 = bn3_g[i] * rsqrtf(bn3_v[i] + EPSB);
        g_b2f[i] = conv2_b[i] * a3 + bn3_b[i] - bn3_m[i] * a3;
    }
    for (int i = tid; i < 64 * 64; i += nt) {
        int kp = i >> 6, o = i & 63;
        float a2 = bn2_g[o] * rsqrtf(bn2_v[o] + EPSB);
        uint32_t h, l;
        sp2h(conv1_w[o * CL + 2 * kp] * a2, conv1_w[o * CL + 2 * kp + 1] * a2, h, l);
        g_c1p[i] = make_uint2(h, l);
    }
    for (int i = tid; i < 3 * 32 * 64; i += nt) {
        int dk = i / 2048, kp = (i >> 6) & 31, o = i & 63;
        float a3 = bn3_g[o] * rsqrtf(bn3_v[o] + EPSB);
        uint32_t h, l;
        sp2h(conv2_w[(o * PL + 2 * kp) * 3 + dk] * a3,
             conv2_w[(o * PL + 2 * kp + 1) * 3 + dk] * a3, h, l);
        g_c2p[i] = make_uint2(h, l);
    }
    for (int i = tid; i < 32 * 128; i += nt) {
        int kp = i >> 7, o = i & 127;
        uint32_t h, l;
        sp2h(conv3_w[o * PL + 2 * kp], conv3_w[o * PL + 2 * kp + 1], h, l);
        g_c3p[i] = make_uint2(h, l);
    }
    for (int i = tid; i < (CIN / 2) * CL; i += nt) {
        int kp = i / CL, o = i % CL;
        uint32_t h, l;
        sp2h(fc1_w[o * CIN + 2 * kp], fc1_w[o * CIN + 2 * kp + 1], h, l);
        g_fc1ph[i] = h;
        g_fc1pl[i] = l;
    }
}

// ---------------- fc1: mma.sync fp16, A unsplit + B 2-term split (R12 verbatim) ----------------
__global__ __launch_bounds__(256) void fc1_tc_kernel(const float* __restrict__ feature,
                                                     const float* __restrict__ fc1_b) {
    __shared__ uint32_t Ax[16][136];
    __shared__ uint32_t Bh[16][136], Bl[16][136];
    __shared__ float biass[128];

    int tid = threadIdx.x;
    long p0l = (long)blockIdx.x * 128;
    int b = (int)(p0l >> 16);
    int pix0 = (int)(p0l & 65535);
    const float* fb = feature + (size_t)b * CIN * NPIX + pix0;
    if (tid < 128) biass[tid] = fc1_b[tid];

    int wid = tid >> 5, lane = tid & 31;
    int warp_m = wid >> 2, warp_n = wid & 3;
    int grp = lane >> 2, qid = lane & 3;
    int pxb = warp_m * 64, ob = warp_n * 32;

    float acc[4][4][4];
#pragma unroll
    for (int mt = 0; mt < 4; mt++)
#pragma unroll
        for (int nt = 0; nt < 4; nt++)
#pragma unroll
            for (int j = 0; j < 4; j++) acc[mt][nt][j] = 0.0f;

    int p2 = tid >> 4, px0 = (tid & 15) * 8;
    float4 A0a, A0b, A1a, A1b;
    uint4 Wh0, Wh1, Wl0, Wl1;
    {
        const float* fa = fb + (size_t)(2 * p2) * NPIX + px0;
        A0a = *(const float4*)fa;          A0b = *(const float4*)(fa + 4);
        A1a = *(const float4*)(fa + NPIX); A1b = *(const float4*)(fa + NPIX + 4);
        const uint32_t* wh = g_fc1ph + p2 * CL + px0;
        const uint32_t* wl = g_fc1pl + p2 * CL + px0;
        Wh0 = *(const uint4*)wh; Wh1 = *(const uint4*)(wh + 4);
        Wl0 = *(const uint4*)wl; Wl1 = *(const uint4*)(wl + 4);
    }
    for (int ch = 0; ch < 8; ch++) {
        __syncthreads();
        {
            uint4 t;
            t.x = pkh(A0a.x, A1a.x); t.y = pkh(A0a.y, A1a.y);
            t.z = pkh(A0a.z, A1a.z); t.w = pkh(A0a.w, A1a.w);
            *(uint4*)&Ax[p2][px0] = t;
            t.x = pkh(A0b.x, A1b.x); t.y = pkh(A0b.y, A1b.y);
            t.z = pkh(A0b.z, A1b.z); t.w = pkh(A0b.w, A1b.w);
            *(uint4*)&Ax[p2][px0 + 4] = t;
            *(uint4*)&Bh[p2][px0] = Wh0;    *(uint4*)&Bh[p2][px0 + 4] = Wh1;
            *(uint4*)&Bl[p2][px0] = Wl0;    *(uint4*)&Bl[p2][px0 + 4] = Wl1;
        }
        __syncthreads();
        if (ch < 7) {
            int c0 = (ch + 1) * 32;
            const float* fa = fb + (size_t)(c0 + 2 * p2) * NPIX + px0;
            A0a = *(const float4*)fa;          A0b = *(const float4*)(fa + 4);
            A1a = *(const float4*)(fa + NPIX); A1b = *(const float4*)(fa + NPIX + 4);
            const uint32_t* wh = g_fc1ph + ((ch + 1) * 16 + p2) * CL + px0;
            const uint32_t* wl = g_fc1pl + ((ch + 1) * 16 + p2) * CL + px0;
            Wh0 = *(const uint4*)wh; Wh1 = *(const uint4*)(wh + 4);
            Wl0 = *(const uint4*)wl; Wl1 = *(const uint4*)(wl + 4);
        }
#pragma unroll
        for (int ks = 0; ks < 2; ks++) {
            int r0 = ks * 8 + qid;
            const uint32_t *ar = Ax[r0], *ar4 = Ax[r0 + 4];
            uint32_t ah[4][4];
#pragma unroll
            for (int mt = 0; mt < 4; mt++) {
                int px = pxb + mt * 16 + grp;
                ah[mt][0] = ar[px];  ah[mt][1] = ar[px + 8];
                ah[mt][2] = ar4[px]; ah[mt][3] = ar4[px + 8];
            }
            const uint32_t *brh = Bh[r0], *brh4 = Bh[r0 + 4];
            const uint32_t *brl = Bl[r0], *brl4 = Bl[r0 + 4];
#pragma unroll
            for (int nt = 0; nt < 4; nt++) {
                int oo = ob + nt * 8 + grp;
                uint32_t bh0 = brh[oo], bh1 = brh4[oo];
                uint32_t bl0 = brl[oo], bl1 = brl4[oo];
#pragma unroll
                for (int mt = 0; mt < 4; mt++) {
                    mma_fp16(acc[mt][nt], ah[mt][0], ah[mt][1], ah[mt][2], ah[mt][3], bh0, bh1);
                    mma_fp16(acc[mt][nt], ah[mt][0], ah[mt][1], ah[mt][2], ah[mt][3], bl0, bl1);
                }
            }
        }
    }
#pragma unroll
    for (int mt = 0; mt < 4; mt++) {
#pragma unroll
        for (int nt = 0; nt < 4; nt++) {
            int px = pix0 + pxb + mt * 16 + grp;
            int oo = ob + nt * 8 + qid * 2;
            float bx = biass[oo], by = biass[oo + 1];
            float2 r0 = make_float2(acc[mt][nt][0] + bx, acc[mt][nt][1] + by);
            float2 r1 = make_float2(acc[mt][nt][2] + bx, acc[mt][nt][3] + by);
            size_t base = ((size_t)b * NPIX + px) * CL + oo;
            *(float2*)&g_xbuf[base] = r0;
            *(float2*)&g_xbuf[base + (size_t)8 * CL] = r1;
        }
    }
}

// ---------------- line: 12 lines/CTA, fp16 2-product MMAs, 2 CTAs/SM ----------------
#define OFF_H1 34816
#define OFF_H2 52224
#define OFF_XP 69632
#define OFF_SO 102400
#define OFF_SW 108544
#define LINE_SMEM 114688

__global__ __launch_bounds__(256) void line_kernel(const float* __restrict__ lines,
                                                   const float* __restrict__ conv3_b,
                                                   const float* __restrict__ fc2_w,
                                                   const float* __restrict__ fc2_b,
                                                   float* __restrict__ out) {
    extern __shared__ char sm_[];
    uint32_t* H0 = (uint32_t*)sm_;                 // [cp 64][RST] fp16x2
    uint32_t* H1 = (uint32_t*)(sm_ + OFF_H1);      // [op 32][RST]
    uint32_t* H2 = (uint32_t*)(sm_ + OFF_H2);      // [op 32][RST]
    __half* XP = (__half*)(sm_ + OFF_XP);
    int4* SO = (int4*)(sm_ + OFF_SO);
    float4* SW = (float4*)(sm_ + OFF_SW);
    float* YB = (float*)sm_;                       // aliases H0/H1 (dead after conv3 frag reads)

    int tid = threadIdx.x;
    int n0 = blockIdx.x * NLC;

    for (int i = tid; i < NLC * 32; i += 256) {
        int line = i >> 5, p = i & 31, n = n0 + line;
        if (n < NB * NL) {
            float lam = (float)p * (1.0f / 31.0f);
            const float* lp = lines + (size_t)n * 4;
            float px = lp[0] * lam + lp[2] * (1.0f - lam) - 0.5f;
            float py = lp[1] * lam + lp[3] * (1.0f - lam) - 0.5f;
            float px0 = fminf(fmaxf(floorf(px), 0.0f), 255.0f);
            float py0 = fminf(fmaxf(floorf(py), 0.0f), 255.0f);
            float px1 = fminf(px0 + 1.0f, 255.0f);
            float py1 = fminf(py0 + 1.0f, 255.0f);
            int ix0 = (int)px0, iy0 = (int)py0, ix1 = (int)px1, iy1 = (int)py1;
            SO[i] = make_int4((ix0 * HW + iy0) * CL, (ix1 * HW + iy0) * CL,
                              (ix0 * HW + iy1) * CL, (ix1 * HW + iy1) * CL);
            SW[i] = make_float4((px1 - px) * (py1 - py), (px - px0) * (py1 - py),
                                (px1 - px) * (py - py0), (px - px0) * (py - py0));
        } else {
            SO[i] = make_int4(0, 0, 0, 0);
            SW[i] = make_float4(0.f, 0.f, 0.f, 0.f);
        }
    }
    {
        uint4 z = make_uint4(0, 0, 0, 0);
        uint4* d = (uint4*)(sm_ + OFF_H1);
        for (int i = tid; i < (OFF_H2 - OFF_H1) / 16; i += 256) d[i] = z;
    }
    __syncthreads();

    // sampling + maxpool + BN1
#pragma unroll
    for (int r = 0; r < 3; r++) {
        int task = tid + r * 256;
        int line = task >> 6, cp = task & 63;
        int n = n0 + line;
        int b = (n < NB * NL) ? (n / NL) : (NB - 1);
        const float* xb = g_xbuf + (size_t)b * NPIX * CL + 2 * cp;
        const int4* so = SO + line * 32;
        const float4* sw = SW + line * 32;
        float m0[8], m1[8];
#pragma unroll
        for (int p = 0; p < 32; p++) {
            int4 off = so[p]; float4 w = sw[p];
            float2 c00 = *(const float2*)(xb + off.x);
            float2 c10 = *(const float2*)(xb + off.y);
            float2 c01 = *(const float2*)(xb + off.z);
            float2 c11 = *(const float2*)(xb + off.w);
            float v0 = w.x * c00.x + w.y * c10.x + w.z * c01.x + w.w * c11.x;
            float v1 = w.x * c00.y + w.y * c10.y + w.z * c01.y + w.w * c11.y;
            int t = p >> 2;
            if ((p & 3) == 0) { m0[t] = v0; m1[t] = v1; }
            else { m0[t] = fmaxf(m0[t], v0); m1[t] = fmaxf(m1[t], v1); }
        }
        float a0 = g_a1[2 * cp], a1v = g_a1[2 * cp + 1];
        float b0 = g_b1c[2 * cp], b1v = g_b1c[2 * cp + 1];
#pragma unroll
        for (int t = 0; t < 8; t++) {
            int row = line * 10 + 1 + t;
            *(__half2*)&XP[row * 128 + 2 * cp] = __floats2half2_rn(m0[t], m1[t]);
            H0[cp * RST + row] = pkh(fmaxf(m0[t] * a0 + b0, 0.f),
                                     fmaxf(m1[t] * a1v + b1v, 0.f));
        }
    }
    __syncthreads();

    int lane = tid & 31, wid = tid >> 5;
    int grp = lane >> 2, qid = lane & 3;
    int wm = wid >> 2, wn = wid & 3;

    // conv1
    {
        float acc[4][2][4] = {};
        for (int ks = 0; ks < 8; ks++) {
            const uint32_t* p0 = H0 + (ks * 8 + qid) * RST;
            const uint32_t* p4 = H0 + (ks * 8 + qid + 4) * RST;
            uint32_t ah[4][4];
#pragma unroll
            for (int mt = 0; mt < 4; mt++) {
                int m = wm * 64 + mt * 16 + grp;
                ah[mt][0] = p0[m]; ah[mt][1] = p0[m + 8];
                ah[mt][2] = p4[m]; ah[mt][3] = p4[m + 8];
            }
#pragma unroll
            for (int nt = 0; nt < 2; nt++) {
                int oo = wn * 16 + nt * 8 + grp;
                uint2 b0 = __ldg(&g_c1p[(ks * 8 + qid) * 64 + oo]);
                uint2 b4 = __ldg(&g_c1p[(ks * 8 + qid + 4) * 64 + oo]);
#pragma unroll
                for (int mt = 0; mt < 4; mt++) {
                    mma_fp16(acc[mt][nt], ah[mt][0], ah[mt][1], ah[mt][2], ah[mt][3], b0.x, b4.x);
                    mma_fp16(acc[mt][nt], ah[mt][0], ah[mt][1], ah[mt][2], ah[mt][3], b0.y, b4.y);
                }
            }
        }
#pragma unroll
        for (int mt = 0; mt < 4; mt++)
#pragma unroll
            for (int nt = 0; nt < 2; nt++) {
                int o = wn * 16 + nt * 8 + qid * 2;
                float bx = g_b1f[o], by = g_b1f[o + 1];
#pragma unroll
                for (int half = 0; half < 2; half++) {
                    int row = wm * 64 + mt * 16 + grp + half * 8;
                    if (row >= 1 && row <= 120 && ((row - 1) % 10) < 8) {
                        H1[(o >> 1) * RST + row] =
                            pkh(fmaxf(acc[mt][nt][half * 2] + bx, 0.f),
                                fmaxf(acc[mt][nt][half * 2 + 1] + by, 0.f));
                    }
                }
            }
    }
    __syncthreads();

    // conv2 (k=3 via row-shifted passes)
    {
        float acc[4][2][4] = {};
        for (int dk = 0; dk < 3; dk++) {
            for (int ks = 0; ks < 4; ks++) {
                const uint32_t* p0 = H1 + (ks * 8 + qid) * RST + (dk - 1);
                const uint32_t* p4 = H1 + (ks * 8 + qid + 4) * RST + (dk - 1);
                uint32_t ah[4][4];
#pragma unroll
                for (int mt = 0; mt < 4; mt++) {
                    int m = wm * 64 + mt * 16 + grp;
                    ah[mt][0] = p0[m]; ah[mt][1] = p0[m + 8];
                    ah[mt][2] = p4[m]; ah[mt][3] = p4[m + 8];
                }
#pragma unroll
                for (int nt = 0; nt < 2; nt++) {
                    int oo = wn * 16 + nt * 8 + grp;
                    uint2 b0 = __ldg(&g_c2p[dk * 2048 + (ks * 8 + qid) * 64 + oo]);
                    uint2 b4 = __ldg(&g_c2p[dk * 2048 + (ks * 8 + qid + 4) * 64 + oo]);
#pragma unroll
                    for (int mt = 0; mt < 4; mt++) {
                        mma_fp16(acc[mt][nt], ah[mt][0], ah[mt][1], ah[mt][2], ah[mt][3], b0.x, b4.x);
                        mma_fp16(acc[mt][nt], ah[mt][0], ah[mt][1], ah[mt][2], ah[mt][3], b0.y, b4.y);
                    }
                }
            }
        }
        __syncthreads();
#pragma unroll
        for (int mt = 0; mt < 4; mt++)
#pragma unroll
            for (int nt = 0; nt < 2; nt++) {
                int o = wn * 16 + nt * 8 + qid * 2;
                float bx = g_b2f[o], by = g_b2f[o + 1];
#pragma unroll
                for (int half = 0; half < 2; half++) {
                    int row = wm * 64 + mt * 16 + grp + half * 8;
                    H2[(o >> 1) * RST + row] =
                        pkh(fmaxf(acc[mt][nt][half * 2] + bx, 0.f),
                            fmaxf(acc[mt][nt][half * 2 + 1] + by, 0.f));
                }
            }
    }
    __syncthreads();

    // conv3 + residual + ReLU -> YB
    {
        float acc[4][4][4] = {};
        for (int ks = 0; ks < 4; ks++) {
            const uint32_t* p0 = H2 + (ks * 8 + qid) * RST;
            const uint32_t* p4 = H2 + (ks * 8 + qid + 4) * RST;
            uint32_t ah[4][4];
#pragma unroll
            for (int mt = 0; mt < 4; mt++) {
                int m = wm * 64 + mt * 16 + grp;
                ah[mt][0] = p0[m]; ah[mt][1] = p0[m + 8];
                ah[mt][2] = p4[m]; ah[mt][3] = p4[m + 8];
            }
#pragma unroll
            for (int nt = 0; nt < 4; nt++) {
                int oo = wn * 32 + nt * 8 + grp;
                uint2 b0 = __ldg(&g_c3p[(ks * 8 + qid) * 128 + oo]);
                uint2 b4 = __ldg(&g_c3p[(ks * 8 + qid + 4) * 128 + oo]);
#pragma unroll
                for (int mt = 0; mt < 4; mt++) {
                    mma_fp16(acc[mt][nt], ah[mt][0], ah[mt][1], ah[mt][2], ah[mt][3], b0.x, b4.x);
                    mma_fp16(acc[mt][nt], ah[mt][0], ah[mt][1], ah[mt][2], ah[mt][3], b0.y, b4.y);
                }
            }
        }
        __syncthreads();   // H2 frag reads complete before YB (aliasing planes) is written
#pragma unroll
        for (int nt = 0; nt < 4; nt++) {
            int oc = wn * 32 + nt * 8 + qid * 2;
            float cbx = __ldg(&conv3_b[oc]), cby = __ldg(&conv3_b[oc + 1]);
#pragma unroll
            for (int mt = 0; mt < 4; mt++)
#pragma unroll
                for (int half = 0; half < 2; half++) {
                    int row = wm * 64 + mt * 16 + grp + half * 8;
                    __half2 xv = *(__half2*)&XP[row * 128 + oc];
                    float y0 = fmaxf(__low2float(xv) + acc[mt][nt][half * 2] + cbx, 0.f);
                    float y1 = fmaxf(__high2float(xv) + acc[mt][nt][half * 2 + 1] + cby, 0.f);
                    *(float2*)&YB[row * 128 + oc] = make_float2(y0, y1);
                }
        }
    }
    __syncthreads();

    // fc2
    if (tid < NLC * 16) {
        int line = tid >> 4, sl = tid & 15;
        int n = n0 + line;
        float s0 = 0.f, s1 = 0.f, s2v = 0.f;
#pragma unroll
        for (int j = 0; j < 8; j++) {
            int c = sl * 8 + j;
            float yv[8];
#pragma unroll
            for (int t = 0; t < 8; t++) yv[t] = YB[(line * 10 + 1 + t) * 128 + c];
            int f = c * 8;
#pragma unroll
            for (int k = 0; k < 3; k++) {
                const float4* fw = (const float4*)(fc2_w + k * 1024 + f);
                float4 wa = __ldg(fw), wb = __ldg(fw + 1);
                float d = yv[0] * wa.x + yv[1] * wa.y + yv[2] * wa.z + yv[3] * wa.w
                        + yv[4] * wb.x + yv[5] * wb.y + yv[6] * wb.z + yv[7] * wb.w;
                if (k == 0) s0 += d; else if (k == 1) s1 += d; else s2v += d;
            }
        }
#pragma unroll
        for (int off = 8; off > 0; off >>= 1) {
            s0 += __shfl_down_sync(0xffffffffu, s0, off, 16);
            s1 += __shfl_down_sync(0xffffffffu, s1, off, 16);
            s2v += __shfl_down_sync(0xffffffffu, s2v, off, 16);
        }
        if (sl == 0 && n < NB * NL) {
            out[(size_t)n * 3 + 0] = s0 + __ldg(&fc2_b[0]);
            out[(size_t)n * 3 + 1] = s1 + __ldg(&fc2_b[1]);
            out[(size_t)n * 3 + 2] = s2v + __ldg(&fc2_b[2]);
        }
    }
}

// ---------------- launch ----------------
extern "C" void kernel_launch(void* const* d_in, const int* in_sizes, int n_in,
                              void* d_out, int out_size) {
    const float* feature = (const float*)d_in[0];
    const float* lines = (const float*)d_in[1];
    float* out = (float*)d_out;

    prep_kernel<<<64, 256>>>((const float*)d_in[2],
        (const float*)d_in[4], (const float*)d_in[5], (const float*)d_in[6], (const float*)d_in[7],
        (const float*)d_in[8], (const float*)d_in[9],
        (const float*)d_in[10], (const float*)d_in[11], (const float*)d_in[12], (const float*)d_in[13],
        (const float*)d_in[14], (const float*)d_in[15],
        (const float*)d_in[16], (const float*)d_in[17], (const float*)d_in[18], (const float*)d_in[19],
        (const float*)d_in[20]);
    fc1_tc_kernel<<<(NB * NPIX) / 128, 256>>>(feature, (const float*)d_in[3]);
    cudaFuncSetAttribute(line_kernel, cudaFuncAttributeMaxDynamicSharedMemorySize, LINE_SMEM);
    int nblk = (NB * NL + NLC - 1) / NLC;
    line_kernel<<<nblk, 256, LINE_SMEM>>>(lines, (const float*)d_in[21],
                                          (const float*)d_in[22], (const float*)d_in[23], out);
}

// round 16
// speedup vs baseline: 2.1567x; 1.2524x over previous
#include <cuda_runtime.h>
#include <cuda_bf16.h>
#include <cuda_fp16.h>
#include <math.h>
#include <stdint.h>

#define NB 2
#define NL 5000
#define HW 256
#define NPIX 65536
#define CIN 256
#define CL 128
#define PL 64
#define EPSB 1e-5f
#define NLC 12
#define RST 136

__device__ float g_xbuf[(size_t)NB * NPIX * CL];
__device__ uint32_t g_fc1p[(CIN / 2) * CL];       // fc1_w fp16x2, [kpair][o]
__device__ float g_a1[CL], g_b1c[CL];
__device__ float g_b1f[PL], g_b2f[PL];
__device__ uint32_t g_c1p[64 * 64];               // conv1 B [kpair][o] fp16x2
__device__ uint32_t g_c2p[3 * 32 * 64];           // conv2 B [dk][kpair][o]
__device__ uint32_t g_c3p[32 * 128];              // conv3 B [kpair][o]

__device__ __forceinline__ uint32_t pkh(float x, float y) {
    __half2 h = __floats2half2_rn(x, y);
    return *reinterpret_cast<uint32_t*>(&h);
}
__device__ __forceinline__ void mma_fp16(float* d, uint32_t a0, uint32_t a1,
                                         uint32_t a2, uint32_t a3,
                                         uint32_t b0, uint32_t b1) {
    asm volatile(
        "mma.sync.aligned.m16n8k16.row.col.f32.f16.f16.f32 "
        "{%0,%1,%2,%3}, {%4,%5,%6,%7}, {%8,%9}, {%0,%1,%2,%3};\n"
        : "+f"(d[0]), "+f"(d[1]), "+f"(d[2]), "+f"(d[3])
        : "r"(a0), "r"(a1), "r"(a2), "r"(a3), "r"(b0), "r"(b1));
}

// ---------------- prep ----------------
__global__ void prep_kernel(const float* __restrict__ fc1_w,
                            const float* __restrict__ bn1_g, const float* __restrict__ bn1_b,
                            const float* __restrict__ bn1_m, const float* __restrict__ bn1_v,
                            const float* __restrict__ conv1_w, const float* __restrict__ conv1_b,
                            const float* __restrict__ bn2_g, const float* __restrict__ bn2_b,
                            const float* __restrict__ bn2_m, const float* __restrict__ bn2_v,
                            const float* __restrict__ conv2_w, const float* __restrict__ conv2_b,
                            const float* __restrict__ bn3_g, const float* __restrict__ bn3_b,
                            const float* __restrict__ bn3_m, const float* __restrict__ bn3_v,
                            const float* __restrict__ conv3_w) {
    int tid = blockIdx.x * blockDim.x + threadIdx.x;
    int nt = gridDim.x * blockDim.x;
    for (int i = tid; i < CL; i += nt) {
        float a = bn1_g[i] * rsqrtf(bn1_v[i] + EPSB);
        g_a1[i] = a;
        g_b1c[i] = bn1_b[i] - bn1_m[i] * a;
    }
    for (int i = tid; i < PL; i += nt) {
        float a2 = bn2_g[i] * rsqrtf(bn2_v[i] + EPSB);
        g_b1f[i] = conv1_b[i] * a2 + bn2_b[i] - bn2_m[i] * a2;
        float a3 = bn3_g[i] * rsqrtf(bn3_v[i] + EPSB);
        g_b2f[i] = conv2_b[i] * a3 + bn3_b[i] - bn3_m[i] * a3;
    }
    for (int i = tid; i < 64 * 64; i += nt) {
        int kp = i >> 6, o = i & 63;
        float a2 = bn2_g[o] * rsqrtf(bn2_v[o] + EPSB);
        g_c1p[i] = pkh(conv1_w[o * CL + 2 * kp] * a2, conv1_w[o * CL + 2 * kp + 1] * a2);
    }
    for (int i = tid; i < 3 * 32 * 64; i += nt) {
        int dk = i / 2048, kp = (i >> 6) & 31, o = i & 63;
        float a3 = bn3_g[o] * rsqrtf(bn3_v[o] + EPSB);
        g_c2p[i] = pkh(conv2_w[(o * PL + 2 * kp) * 3 + dk] * a3,
                       conv2_w[(o * PL + 2 * kp + 1) * 3 + dk] * a3);
    }
    for (int i = tid; i < 32 * 128; i += nt) {
        int kp = i >> 7, o = i & 127;
        g_c3p[i] = pkh(conv3_w[o * PL + 2 * kp], conv3_w[o * PL + 2 * kp + 1]);
    }
    for (int i = tid; i < (CIN / 2) * CL; i += nt) {
        int kp = i / CL, o = i % CL;
        g_fc1p[i] = pkh(fc1_w[o * CIN + 2 * kp], fc1_w[o * CIN + 2 * kp + 1]);
    }
}

// ---------------- fc1: mma.sync fp16 single-product ----------------
__global__ __launch_bounds__(256) void fc1_tc_kernel(const float* __restrict__ feature,
                                                     const float* __restrict__ fc1_b) {
    __shared__ uint32_t Ax[16][136];
    __shared__ uint32_t Bx[16][136];
    __shared__ float biass[128];

    int tid = threadIdx.x;
    long p0l = (long)blockIdx.x * 128;
    int b = (int)(p0l >> 16);
    int pix0 = (int)(p0l & 65535);
    const float* fb = feature + (size_t)b * CIN * NPIX + pix0;
    if (tid < 128) biass[tid] = fc1_b[tid];

    int wid = tid >> 5, lane = tid & 31;
    int warp_m = wid >> 2, warp_n = wid & 3;
    int grp = lane >> 2, qid = lane & 3;
    int pxb = warp_m * 64, ob = warp_n * 32;

    float acc[4][4][4];
#pragma unroll
    for (int mt = 0; mt < 4; mt++)
#pragma unroll
        for (int nt = 0; nt < 4; nt++)
#pragma unroll
            for (int j = 0; j < 4; j++) acc[mt][nt][j] = 0.0f;

    int p2 = tid >> 4, px0 = (tid & 15) * 8;
    float4 A0a, A0b, A1a, A1b;
    uint4 W0, W1;
    {
        const float* fa = fb + (size_t)(2 * p2) * NPIX + px0;
        A0a = *(const float4*)fa;          A0b = *(const float4*)(fa + 4);
        A1a = *(const float4*)(fa + NPIX); A1b = *(const float4*)(fa + NPIX + 4);
        const uint32_t* wh = g_fc1p + p2 * CL + px0;
        W0 = *(const uint4*)wh; W1 = *(const uint4*)(wh + 4);
    }
    for (int ch = 0; ch < 8; ch++) {
        __syncthreads();
        {
            uint4 t;
            t.x = pkh(A0a.x, A1a.x); t.y = pkh(A0a.y, A1a.y);
            t.z = pkh(A0a.z, A1a.z); t.w = pkh(A0a.w, A1a.w);
            *(uint4*)&Ax[p2][px0] = t;
            t.x = pkh(A0b.x, A1b.x); t.y = pkh(A0b.y, A1b.y);
            t.z = pkh(A0b.z, A1b.z); t.w = pkh(A0b.w, A1b.w);
            *(uint4*)&Ax[p2][px0 + 4] = t;
            *(uint4*)&Bx[p2][px0] = W0;
            *(uint4*)&Bx[p2][px0 + 4] = W1;
        }
        __syncthreads();
        if (ch < 7) {
            int c0 = (ch + 1) * 32;
            const float* fa = fb + (size_t)(c0 + 2 * p2) * NPIX + px0;
            A0a = *(const float4*)fa;          A0b = *(const float4*)(fa + 4);
            A1a = *(const float4*)(fa + NPIX); A1b = *(const float4*)(fa + NPIX + 4);
            const uint32_t* wh = g_fc1p + ((ch + 1) * 16 + p2) * CL + px0;
            W0 = *(const uint4*)wh; W1 = *(const uint4*)(wh + 4);
        }
#pragma unroll
        for (int ks = 0; ks < 2; ks++) {
            int r0 = ks * 8 + qid;
            const uint32_t *ar = Ax[r0], *ar4 = Ax[r0 + 4];
            uint32_t ah[4][4];
#pragma unroll
            for (int mt = 0; mt < 4; mt++) {
                int px = pxb + mt * 16 + grp;
                ah[mt][0] = ar[px];  ah[mt][1] = ar[px + 8];
                ah[mt][2] = ar4[px]; ah[mt][3] = ar4[px + 8];
            }
            const uint32_t *br = Bx[r0], *br4 = Bx[r0 + 4];
#pragma unroll
            for (int nt = 0; nt < 4; nt++) {
                int oo = ob + nt * 8 + grp;
                uint32_t b0 = br[oo], b1 = br4[oo];
#pragma unroll
                for (int mt = 0; mt < 4; mt++)
                    mma_fp16(acc[mt][nt], ah[mt][0], ah[mt][1], ah[mt][2], ah[mt][3], b0, b1);
            }
        }
    }
#pragma unroll
    for (int mt = 0; mt < 4; mt++) {
#pragma unroll
        for (int nt = 0; nt < 4; nt++) {
            int px = pix0 + pxb + mt * 16 + grp;
            int oo = ob + nt * 8 + qid * 2;
            float bx = biass[oo], by = biass[oo + 1];
            float2 r0 = make_float2(acc[mt][nt][0] + bx, acc[mt][nt][1] + by);
            float2 r1 = make_float2(acc[mt][nt][2] + bx, acc[mt][nt][3] + by);
            size_t base = ((size_t)b * NPIX + px) * CL + oo;
            *(float2*)&g_xbuf[base] = r0;
            *(float2*)&g_xbuf[base + (size_t)8 * CL] = r1;
        }
    }
}

// ---------------- line: 12 lines/CTA, single-product fp16 MMAs ----------------
#define OFF_H1 34816
#define OFF_H2 52224
#define OFF_XP 69632
#define OFF_SO 102400
#define OFF_SW 108544
#define LINE_SMEM 114688

__global__ __launch_bounds__(256) void line_kernel(const float* __restrict__ lines,
                                                   const float* __restrict__ conv3_b,
                                                   const float* __restrict__ fc2_w,
                                                   const float* __restrict__ fc2_b,
                                                   float* __restrict__ out) {
    extern __shared__ char sm_[];
    uint32_t* H0 = (uint32_t*)sm_;
    uint32_t* H1 = (uint32_t*)(sm_ + OFF_H1);
    uint32_t* H2 = (uint32_t*)(sm_ + OFF_H2);
    __half* XP = (__half*)(sm_ + OFF_XP);
    int4* SO = (int4*)(sm_ + OFF_SO);
    float4* SW = (float4*)(sm_ + OFF_SW);
    float* YB = (float*)sm_;

    int tid = threadIdx.x;
    int n0 = blockIdx.x * NLC;

    for (int i = tid; i < NLC * 32; i += 256) {
        int line = i >> 5, p = i & 31, n = n0 + line;
        if (n < NB * NL) {
            float lam = (float)p * (1.0f / 31.0f);
            const float* lp = lines + (size_t)n * 4;
            float px = lp[0] * lam + lp[2] * (1.0f - lam) - 0.5f;
            float py = lp[1] * lam + lp[3] * (1.0f - lam) - 0.5f;
            float px0 = fminf(fmaxf(floorf(px), 0.0f), 255.0f);
            float py0 = fminf(fmaxf(floorf(py), 0.0f), 255.0f);
            float px1 = fminf(px0 + 1.0f, 255.0f);
            float py1 = fminf(py0 + 1.0f, 255.0f);
            int ix0 = (int)px0, iy0 = (int)py0, ix1 = (int)px1, iy1 = (int)py1;
            SO[i] = make_int4((ix0 * HW + iy0) * CL, (ix1 * HW + iy0) * CL,
                              (ix0 * HW + iy1) * CL, (ix1 * HW + iy1) * CL);
            SW[i] = make_float4((px1 - px) * (py1 - py), (px - px0) * (py1 - py),
                                (px1 - px) * (py - py0), (px - px0) * (py - py0));
        } else {
            SO[i] = make_int4(0, 0, 0, 0);
            SW[i] = make_float4(0.f, 0.f, 0.f, 0.f);
        }
    }
    {
        uint4 z = make_uint4(0, 0, 0, 0);
        uint4* d = (uint4*)(sm_ + OFF_H1);
        for (int i = tid; i < (OFF_H2 - OFF_H1) / 16; i += 256) d[i] = z;
    }
    __syncthreads();

#pragma unroll
    for (int r = 0; r < 3; r++) {
        int task = tid + r * 256;
        int line = task >> 6, cp = task & 63;
        int n = n0 + line;
        int b = (n < NB * NL) ? (n / NL) : (NB - 1);
        const float* xb = g_xbuf + (size_t)b * NPIX * CL + 2 * cp;
        const int4* so = SO + line * 32;
        const float4* sw = SW + line * 32;
        float m0[8], m1[8];
#pragma unroll
        for (int p = 0; p < 32; p++) {
            int4 off = so[p]; float4 w = sw[p];
            float2 c00 = *(const float2*)(xb + off.x);
            float2 c10 = *(const float2*)(xb + off.y);
            float2 c01 = *(const float2*)(xb + off.z);
            float2 c11 = *(const float2*)(xb + off.w);
            float v0 = w.x * c00.x + w.y * c10.x + w.z * c01.x + w.w * c11.x;
            float v1 = w.x * c00.y + w.y * c10.y + w.z * c01.y + w.w * c11.y;
            int t = p >> 2;
            if ((p & 3) == 0) { m0[t] = v0; m1[t] = v1; }
            else { m0[t] = fmaxf(m0[t], v0); m1[t] = fmaxf(m1[t], v1); }
        }
        float a0 = g_a1[2 * cp], a1v = g_a1[2 * cp + 1];
        float b0 = g_b1c[2 * cp], b1v = g_b1c[2 * cp + 1];
#pragma unroll
        for (int t = 0; t < 8; t++) {
            int row = line * 10 + 1 + t;
            *(__half2*)&XP[row * 128 + 2 * cp] = __floats2half2_rn(m0[t], m1[t]);
            H0[cp * RST + row] = pkh(fmaxf(m0[t] * a0 + b0, 0.f),
                                     fmaxf(m1[t] * a1v + b1v, 0.f));
        }
    }
    __syncthreads();

    int lane = tid & 31, wid = tid >> 5;
    int grp = lane >> 2, qid = lane & 3;
    int wm = wid >> 2, wn = wid & 3;

    // conv1
    {
        float acc[4][2][4] = {};
        for (int ks = 0; ks < 8; ks++) {
            const uint32_t* p0 = H0 + (ks * 8 + qid) * RST;
            const uint32_t* p4 = H0 + (ks * 8 + qid + 4) * RST;
            uint32_t ah[4][4];
#pragma unroll
            for (int mt = 0; mt < 4; mt++) {
                int m = wm * 64 + mt * 16 + grp;
                ah[mt][0] = p0[m]; ah[mt][1] = p0[m + 8];
                ah[mt][2] = p4[m]; ah[mt][3] = p4[m + 8];
            }
#pragma unroll
            for (int nt = 0; nt < 2; nt++) {
                int oo = wn * 16 + nt * 8 + grp;
                uint32_t b0 = __ldg(&g_c1p[(ks * 8 + qid) * 64 + oo]);
                uint32_t b4 = __ldg(&g_c1p[(ks * 8 + qid + 4) * 64 + oo]);
#pragma unroll
                for (int mt = 0; mt < 4; mt++)
                    mma_fp16(acc[mt][nt], ah[mt][0], ah[mt][1], ah[mt][2], ah[mt][3], b0, b4);
            }
        }
#pragma unroll
        for (int mt = 0; mt < 4; mt++)
#pragma unroll
            for (int nt = 0; nt < 2; nt++) {
                int o = wn * 16 + nt * 8 + qid * 2;
                float bx = g_b1f[o], by = g_b1f[o + 1];
#pragma unroll
                for (int half = 0; half < 2; half++) {
                    int row = wm * 64 + mt * 16 + grp + half * 8;
                    if (row >= 1 && row <= 120 && ((row - 1) % 10) < 8) {
                        H1[(o >> 1) * RST + row] =
                            pkh(fmaxf(acc[mt][nt][half * 2] + bx, 0.f),
                                fmaxf(acc[mt][nt][half * 2 + 1] + by, 0.f));
                    }
                }
            }
    }
    __syncthreads();

    // conv2
    {
        float acc[4][2][4] = {};
        for (int dk = 0; dk < 3; dk++) {
            for (int ks = 0; ks < 4; ks++) {
                const uint32_t* p0 = H1 + (ks * 8 + qid) * RST + (dk - 1);
                const uint32_t* p4 = H1 + (ks * 8 + qid + 4) * RST + (dk - 1);
                uint32_t ah[4][4];
#pragma unroll
                for (int mt = 0; mt < 4; mt++) {
                    int m = wm * 64 + mt * 16 + grp;
                    ah[mt][0] = p0[m]; ah[mt][1] = p0[m + 8];
                    ah[mt][2] = p4[m]; ah[mt][3] = p4[m + 8];
                }
#pragma unroll
                for (int nt = 0; nt < 2; nt++) {
                    int oo = wn * 16 + nt * 8 + grp;
                    uint32_t b0 = __ldg(&g_c2p[dk * 2048 + (ks * 8 + qid) * 64 + oo]);
                    uint32_t b4 = __ldg(&g_c2p[dk * 2048 + (ks * 8 + qid + 4) * 64 + oo]);
#pragma unroll
                    for (int mt = 0; mt < 4; mt++)
                        mma_fp16(acc[mt][nt], ah[mt][0], ah[mt][1], ah[mt][2], ah[mt][3], b0, b4);
                }
            }
        }
        __syncthreads();
#pragma unroll
        for (int mt = 0; mt < 4; mt++)
#pragma unroll
            for (int nt = 0; nt < 2; nt++) {
                int o = wn * 16 + nt * 8 + qid * 2;
                float bx = g_b2f[o], by = g_b2f[o + 1];
#pragma unroll
                for (int half = 0; half < 2; half++) {
                    int row = wm * 64 + mt * 16 + grp + half * 8;
                    H2[(o >> 1) * RST + row] =
                        pkh(fmaxf(acc[mt][nt][half * 2] + bx, 0.f),
                            fmaxf(acc[mt][nt][half * 2 + 1] + by, 0.f));
                }
            }
    }
    __syncthreads();

    // conv3 + residual + ReLU
    {
        float acc[4][4][4] = {};
        for (int ks = 0; ks < 4; ks++) {
            const uint32_t* p0 = H2 + (ks * 8 + qid) * RST;
            const uint32_t* p4 = H2 + (ks * 8 + qid + 4) * RST;
            uint32_t ah[4][4];
#pragma unroll
            for (int mt = 0; mt < 4; mt++) {
                int m = wm * 64 + mt * 16 + grp;
                ah[mt][0] = p0[m]; ah[mt][1] = p0[m + 8];
                ah[mt][2] = p4[m]; ah[mt][3] = p4[m + 8];
            }
#pragma unroll
            for (int nt = 0; nt < 4; nt++) {
                int oo = wn * 32 + nt * 8 + grp;
                uint32_t b0 = __ldg(&g_c3p[(ks * 8 + qid) * 128 + oo]);
                uint32_t b4 = __ldg(&g_c3p[(ks * 8 + qid + 4) * 128 + oo]);
#pragma unroll
                for (int mt = 0; mt < 4; mt++)
                    mma_fp16(acc[mt][nt], ah[mt][0], ah[mt][1], ah[mt][2], ah[mt][3], b0, b4);
            }
        }
        __syncthreads();
#pragma unroll
        for (int nt = 0; nt < 4; nt++) {
            int oc = wn * 32 + nt * 8 + qid * 2;
            float cbx = __ldg(&conv3_b[oc]), cby = __ldg(&conv3_b[oc + 1]);
#pragma unroll
            for (int mt = 0; mt < 4; mt++)
#pragma unroll
                for (int half = 0; half < 2; half++) {
                    int row = wm * 64 + mt * 16 + grp + half * 8;
                    __half2 xv = *(__half2*)&XP[row * 128 + oc];
                    float y0 = fmaxf(__low2float(xv) + acc[mt][nt][half * 2] + cbx, 0.f);
                    float y1 = fmaxf(__high2float(xv) + acc[mt][nt][half * 2 + 1] + cby, 0.f);
                    *(float2*)&YB[row * 128 + oc] = make_float2(y0, y1);
                }
        }
    }
    __syncthreads();

    // fc2
    if (tid < NLC * 16) {
        int line = tid >> 4, sl = tid & 15;
        int n = n0 + line;
        float s0 = 0.f, s1 = 0.f, s2v = 0.f;
#pragma unroll
        for (int j = 0; j < 8; j++) {
            int c = sl * 8 + j;
            float yv[8];
#pragma unroll
            for (int t = 0; t < 8; t++) yv[t] = YB[(line * 10 + 1 + t) * 128 + c];
            int f = c * 8;
#pragma unroll
            for (int k = 0; k < 3; k++) {
                const float4* fw = (const float4*)(fc2_w + k * 1024 + f);
                float4 wa = __ldg(fw), wb = __ldg(fw + 1);
                float d = yv[0] * wa.x + yv[1] * wa.y + yv[2] * wa.z + yv[3] * wa.w
                        + yv[4] * wb.x + yv[5] * wb.y + yv[6] * wb.z + yv[7] * wb.w;
                if (k == 0) s0 += d; else if (k == 1) s1 += d; else s2v += d;
            }
        }
#pragma unroll
        for (int off = 8; off > 0; off >>= 1) {
            s0 += __shfl_down_sync(0xffffffffu, s0, off, 16);
            s1 += __shfl_down_sync(0xffffffffu, s1, off, 16);
            s2v += __shfl_down_sync(0xffffffffu, s2v, off, 16);
        }
        if (sl == 0 && n < NB * NL) {
            out[(size_t)n * 3 + 0] = s0 + __ldg(&fc2_b[0]);
            out[(size_t)n * 3 + 1] = s1 + __ldg(&fc2_b[1]);
            out[(size_t)n * 3 + 2] = s2v + __ldg(&fc2_b[2]);
        }
    }
}

// ---------------- launch ----------------
extern "C" void kernel_launch(void* const* d_in, const int* in_sizes, int n_in,
                              void* d_out, int out_size) {
    const float* feature = (const float*)d_in[0];
    const float* lines = (const float*)d_in[1];
    float* out = (float*)d_out;

    prep_kernel<<<64, 256>>>((const float*)d_in[2],
        (const float*)d_in[4], (const float*)d_in[5], (const float*)d_in[6], (const float*)d_in[7],
        (const float*)d_in[8], (const float*)d_in[9],
        (const float*)d_in[10], (const float*)d_in[11], (const float*)d_in[12], (const float*)d_in[13],
        (const float*)d_in[14], (const float*)d_in[15],
        (const float*)d_in[16], (const float*)d_in[17], (const float*)d_in[18], (const float*)d_in[19],
        (const float*)d_in[20]);
    fc1_tc_kernel<<<(NB * NPIX) / 128, 256>>>(feature, (const float*)d_in[3]);
    cudaFuncSetAttribute(line_kernel, cudaFuncAttributeMaxDynamicSharedMemorySize, LINE_SMEM);
    int nblk = (NB * NL + NLC - 1) / NLC;
    line_kernel<<<nblk, 256, LINE_SMEM>>>(lines, (const float*)d_in[21],
                                          (const float*)d_in[22], (const float*)d_in[23], out);
}

// round 17
// speedup vs baseline: 2.3854x; 1.1060x over previous
#include <cuda_runtime.h>
#include <cuda_bf16.h>
#include <cuda_fp16.h>
#include <math.h>
#include <stdint.h>

#define NB 2
#define NL 5000
#define HW 256
#define NPIX 65536
#define CIN 256
#define CL 128
#define PL 64
#define EPSB 1e-5f
#define NLC 12
#define RST 136

__device__ __half g_xbufh[(size_t)NB * NPIX * CL];   // fc1 output, fp16, [b][pix][c] (32 MB)
__device__ uint32_t g_fc1p[(CIN / 2) * CL];          // fc1_w fp16x2, [kpair][o]
__device__ float g_a1[CL], g_b1c[CL];
__device__ float g_b1f[PL], g_b2f[PL];
__device__ uint32_t g_c1p[64 * 64];                  // conv1 B [kpair][o] fp16x2
__device__ uint32_t g_c2p[3 * 32 * 64];              // conv2 B [dk][kpair][o]
__device__ uint32_t g_c3p[32 * 128];                 // conv3 B [kpair][o]

__device__ __forceinline__ uint32_t pkh(float x, float y) {
    __half2 h = __floats2half2_rn(x, y);
    return *reinterpret_cast<uint32_t*>(&h);
}
__device__ __forceinline__ void mma_fp16(float* d, uint32_t a0, uint32_t a1,
                                         uint32_t a2, uint32_t a3,
                                         uint32_t b0, uint32_t b1) {
    asm volatile(
        "mma.sync.aligned.m16n8k16.row.col.f32.f16.f16.f32 "
        "{%0,%1,%2,%3}, {%4,%5,%6,%7}, {%8,%9}, {%0,%1,%2,%3};\n"
        : "+f"(d[0]), "+f"(d[1]), "+f"(d[2]), "+f"(d[3])
        : "r"(a0), "r"(a1), "r"(a2), "r"(a3), "r"(b0), "r"(b1));
}

// ---------------- prep ----------------
__global__ void prep_kernel(const float* __restrict__ fc1_w,
                            const float* __restrict__ bn1_g, const float* __restrict__ bn1_b,
                            const float* __restrict__ bn1_m, const float* __restrict__ bn1_v,
                            const float* __restrict__ conv1_w, const float* __restrict__ conv1_b,
                            const float* __restrict__ bn2_g, const float* __restrict__ bn2_b,
                            const float* __restrict__ bn2_m, const float* __restrict__ bn2_v,
                            const float* __restrict__ conv2_w, const float* __restrict__ conv2_b,
                            const float* __restrict__ bn3_g, const float* __restrict__ bn3_b,
                            const float* __restrict__ bn3_m, const float* __restrict__ bn3_v,
                            const float* __restrict__ conv3_w) {
    int tid = blockIdx.x * blockDim.x + threadIdx.x;
    int nt = gridDim.x * blockDim.x;
    for (int i = tid; i < CL; i += nt) {
        float a = bn1_g[i] * rsqrtf(bn1_v[i] + EPSB);
        g_a1[i] = a;
        g_b1c[i] = bn1_b[i] - bn1_m[i] * a;
    }
    for (int i = tid; i < PL; i += nt) {
        float a2 = bn2_g[i] * rsqrtf(bn2_v[i] + EPSB);
        g_b1f[i] = conv1_b[i] * a2 + bn2_b[i] - bn2_m[i] * a2;
        float a3 = bn3_g[i] * rsqrtf(bn3_v[i] + EPSB);
        g_b2f[i] = conv2_b[i] * a3 + bn3_b[i] - bn3_m[i] * a3;
    }
    for (int i = tid; i < 64 * 64; i += nt) {
        int kp = i >> 6, o = i & 63;
        float a2 = bn2_g[o] * rsqrtf(bn2_v[o] + EPSB);
        g_c1p[i] = pkh(conv1_w[o * CL + 2 * kp] * a2, conv1_w[o * CL + 2 * kp + 1] * a2);
    }
    for (int i = tid; i < 3 * 32 * 64; i += nt) {
        int dk = i / 2048, kp = (i >> 6) & 31, o = i & 63;
        float a3 = bn3_g[o] * rsqrtf(bn3_v[o] + EPSB);
        g_c2p[i] = pkh(conv2_w[(o * PL + 2 * kp) * 3 + dk] * a3,
                       conv2_w[(o * PL + 2 * kp + 1) * 3 + dk] * a3);
    }
    for (int i = tid; i < 32 * 128; i += nt) {
        int kp = i >> 7, o = i & 127;
        g_c3p[i] = pkh(conv3_w[o * PL + 2 * kp], conv3_w[o * PL + 2 * kp + 1]);
    }
    for (int i = tid; i < (CIN / 2) * CL; i += nt) {
        int kp = i / CL, o = i % CL;
        g_fc1p[i] = pkh(fc1_w[o * CIN + 2 * kp], fc1_w[o * CIN + 2 * kp + 1]);
    }
}

// ---------------- fc1: mma.sync fp16 single-product, fp16 output ----------------
__global__ __launch_bounds__(256) void fc1_tc_kernel(const float* __restrict__ feature,
                                                     const float* __restrict__ fc1_b) {
    __shared__ uint32_t Ax[16][136];
    __shared__ uint32_t Bx[16][136];
    __shared__ float biass[128];

    int tid = threadIdx.x;
    long p0l = (long)blockIdx.x * 128;
    int b = (int)(p0l >> 16);
    int pix0 = (int)(p0l & 65535);
    const float* fb = feature + (size_t)b * CIN * NPIX + pix0;
    if (tid < 128) biass[tid] = fc1_b[tid];

    int wid = tid >> 5, lane = tid & 31;
    int warp_m = wid >> 2, warp_n = wid & 3;
    int grp = lane >> 2, qid = lane & 3;
    int pxb = warp_m * 64, ob = warp_n * 32;

    float acc[4][4][4];
#pragma unroll
    for (int mt = 0; mt < 4; mt++)
#pragma unroll
        for (int nt = 0; nt < 4; nt++)
#pragma unroll
            for (int j = 0; j < 4; j++) acc[mt][nt][j] = 0.0f;

    int p2 = tid >> 4, px0 = (tid & 15) * 8;
    float4 A0a, A0b, A1a, A1b;
    uint4 W0, W1;
    {
        const float* fa = fb + (size_t)(2 * p2) * NPIX + px0;
        A0a = *(const float4*)fa;          A0b = *(const float4*)(fa + 4);
        A1a = *(const float4*)(fa + NPIX); A1b = *(const float4*)(fa + NPIX + 4);
        const uint32_t* wh = g_fc1p + p2 * CL + px0;
        W0 = *(const uint4*)wh; W1 = *(const uint4*)(wh + 4);
    }
    for (int ch = 0; ch < 8; ch++) {
        __syncthreads();
        {
            uint4 t;
            t.x = pkh(A0a.x, A1a.x); t.y = pkh(A0a.y, A1a.y);
            t.z = pkh(A0a.z, A1a.z); t.w = pkh(A0a.w, A1a.w);
            *(uint4*)&Ax[p2][px0] = t;
            t.x = pkh(A0b.x, A1b.x); t.y = pkh(A0b.y, A1b.y);
            t.z = pkh(A0b.z, A1b.z); t.w = pkh(A0b.w, A1b.w);
            *(uint4*)&Ax[p2][px0 + 4] = t;
            *(uint4*)&Bx[p2][px0] = W0;
            *(uint4*)&Bx[p2][px0 + 4] = W1;
        }
        __syncthreads();
        if (ch < 7) {
            int c0 = (ch + 1) * 32;
            const float* fa = fb + (size_t)(c0 + 2 * p2) * NPIX + px0;
            A0a = *(const float4*)fa;          A0b = *(const float4*)(fa + 4);
            A1a = *(const float4*)(fa + NPIX); A1b = *(const float4*)(fa + NPIX + 4);
            const uint32_t* wh = g_fc1p + ((ch + 1) * 16 + p2) * CL + px0;
            W0 = *(const uint4*)wh; W1 = *(const uint4*)(wh + 4);
        }
#pragma unroll
        for (int ks = 0; ks < 2; ks++) {
            int r0 = ks * 8 + qid;
            const uint32_t *ar = Ax[r0], *ar4 = Ax[r0 + 4];
            uint32_t ah[4][4];
#pragma unroll
            for (int mt = 0; mt < 4; mt++) {
                int px = pxb + mt * 16 + grp;
                ah[mt][0] = ar[px];  ah[mt][1] = ar[px + 8];
                ah[mt][2] = ar4[px]; ah[mt][3] = ar4[px + 8];
            }
            const uint32_t *br = Bx[r0], *br4 = Bx[r0 + 4];
#pragma unroll
            for (int nt = 0; nt < 4; nt++) {
                int oo = ob + nt * 8 + grp;
                uint32_t b0 = br[oo], b1 = br4[oo];
#pragma unroll
                for (int mt = 0; mt < 4; mt++)
                    mma_fp16(acc[mt][nt], ah[mt][0], ah[mt][1], ah[mt][2], ah[mt][3], b0, b1);
            }
        }
    }
#pragma unroll
    for (int mt = 0; mt < 4; mt++) {
#pragma unroll
        for (int nt = 0; nt < 4; nt++) {
            int px = pix0 + pxb + mt * 16 + grp;
            int oo = ob + nt * 8 + qid * 2;
            float bx = biass[oo], by = biass[oo + 1];
            size_t base = ((size_t)b * NPIX + px) * CL + oo;
            *(__half2*)&g_xbufh[base] =
                __floats2half2_rn(acc[mt][nt][0] + bx, acc[mt][nt][1] + by);
            *(__half2*)&g_xbufh[base + (size_t)8 * CL] =
                __floats2half2_rn(acc[mt][nt][2] + bx, acc[mt][nt][3] + by);
        }
    }
}

// ---------------- line: 12 lines/CTA, single-product fp16 MMAs, fp16 gathers ----------------
#define OFF_H1 34816
#define OFF_H2 52224
#define OFF_XP 69632
#define OFF_SO 102400
#define OFF_SW 108544
#define LINE_SMEM 114688

__global__ __launch_bounds__(256) void line_kernel(const float* __restrict__ lines,
                                                   const float* __restrict__ conv3_b,
                                                   const float* __restrict__ fc2_w,
                                                   const float* __restrict__ fc2_b,
                                                   float* __restrict__ out) {
    extern __shared__ char sm_[];
    uint32_t* H0 = (uint32_t*)sm_;
    uint32_t* H1 = (uint32_t*)(sm_ + OFF_H1);
    uint32_t* H2 = (uint32_t*)(sm_ + OFF_H2);
    __half* XP = (__half*)(sm_ + OFF_XP);
    int4* SO = (int4*)(sm_ + OFF_SO);
    float4* SW = (float4*)(sm_ + OFF_SW);
    float* YB = (float*)sm_;

    int tid = threadIdx.x;
    int n0 = blockIdx.x * NLC;

    for (int i = tid; i < NLC * 32; i += 256) {
        int line = i >> 5, p = i & 31, n = n0 + line;
        if (n < NB * NL) {
            float lam = (float)p * (1.0f / 31.0f);
            const float* lp = lines + (size_t)n * 4;
            float px = lp[0] * lam + lp[2] * (1.0f - lam) - 0.5f;
            float py = lp[1] * lam + lp[3] * (1.0f - lam) - 0.5f;
            float px0 = fminf(fmaxf(floorf(px), 0.0f), 255.0f);
            float py0 = fminf(fmaxf(floorf(py), 0.0f), 255.0f);
            float px1 = fminf(px0 + 1.0f, 255.0f);
            float py1 = fminf(py0 + 1.0f, 255.0f);
            int ix0 = (int)px0, iy0 = (int)py0, ix1 = (int)px1, iy1 = (int)py1;
            SO[i] = make_int4((ix0 * HW + iy0) * CL, (ix1 * HW + iy0) * CL,
                              (ix0 * HW + iy1) * CL, (ix1 * HW + iy1) * CL);
            SW[i] = make_float4((px1 - px) * (py1 - py), (px - px0) * (py1 - py),
                                (px1 - px) * (py - py0), (px - px0) * (py - py0));
        } else {
            SO[i] = make_int4(0, 0, 0, 0);
            SW[i] = make_float4(0.f, 0.f, 0.f, 0.f);
        }
    }
    {
        uint4 z = make_uint4(0, 0, 0, 0);
        uint4* d = (uint4*)(sm_ + OFF_H1);
        for (int i = tid; i < (OFF_H2 - OFF_H1) / 16; i += 256) d[i] = z;
    }
    __syncthreads();

    // sampling + maxpool + BN1 (fp16 gathers)
#pragma unroll
    for (int r = 0; r < 3; r++) {
        int task = tid + r * 256;
        int line = task >> 6, cp = task & 63;
        int n = n0 + line;
        int b = (n < NB * NL) ? (n / NL) : (NB - 1);
        const __half* xb = g_xbufh + (size_t)b * NPIX * CL + 2 * cp;
        const int4* so = SO + line * 32;
        const float4* sw = SW + line * 32;
        float m0[8], m1[8];
#pragma unroll
        for (int p = 0; p < 32; p++) {
            int4 off = so[p]; float4 w = sw[p];
            float2 c00 = __half22float2(*(const __half2*)(xb + off.x));
            float2 c10 = __half22float2(*(const __half2*)(xb + off.y));
            float2 c01 = __half22float2(*(const __half2*)(xb + off.z));
            float2 c11 = __half22float2(*(const __half2*)(xb + off.w));
            float v0 = w.x * c00.x + w.y * c10.x + w.z * c01.x + w.w * c11.x;
            float v1 = w.x * c00.y + w.y * c10.y + w.z * c01.y + w.w * c11.y;
            int t = p >> 2;
            if ((p & 3) == 0) { m0[t] = v0; m1[t] = v1; }
            else { m0[t] = fmaxf(m0[t], v0); m1[t] = fmaxf(m1[t], v1); }
        }
        float a0 = g_a1[2 * cp], a1v = g_a1[2 * cp + 1];
        float b0 = g_b1c[2 * cp], b1v = g_b1c[2 * cp + 1];
#pragma unroll
        for (int t = 0; t < 8; t++) {
            int row = line * 10 + 1 + t;
            *(__half2*)&XP[row * 128 + 2 * cp] = __floats2half2_rn(m0[t], m1[t]);
            H0[cp * RST + row] = pkh(fmaxf(m0[t] * a0 + b0, 0.f),
                                     fmaxf(m1[t] * a1v + b1v, 0.f));
        }
    }
    __syncthreads();

    int lane = tid & 31, wid = tid >> 5;
    int grp = lane >> 2, qid = lane & 3;
    int wm = wid >> 2, wn = wid & 3;

    // conv1
    {
        float acc[4][2][4] = {};
        for (int ks = 0; ks < 8; ks++) {
            const uint32_t* p0 = H0 + (ks * 8 + qid) * RST;
            const uint32_t* p4 = H0 + (ks * 8 + qid + 4) * RST;
            uint32_t ah[4][4];
#pragma unroll
            for (int mt = 0; mt < 4; mt++) {
                int m = wm * 64 + mt * 16 + grp;
                ah[mt][0] = p0[m]; ah[mt][1] = p0[m + 8];
                ah[mt][2] = p4[m]; ah[mt][3] = p4[m + 8];
            }
#pragma unroll
            for (int nt = 0; nt < 2; nt++) {
                int oo = wn * 16 + nt * 8 + grp;
                uint32_t b0 = __ldg(&g_c1p[(ks * 8 + qid) * 64 + oo]);
                uint32_t b4 = __ldg(&g_c1p[(ks * 8 + qid + 4) * 64 + oo]);
#pragma unroll
                for (int mt = 0; mt < 4; mt++)
                    mma_fp16(acc[mt][nt], ah[mt][0], ah[mt][1], ah[mt][2], ah[mt][3], b0, b4);
            }
        }
#pragma unroll
        for (int mt = 0; mt < 4; mt++)
#pragma unroll
            for (int nt = 0; nt < 2; nt++) {
                int o = wn * 16 + nt * 8 + qid * 2;
                float bx = g_b1f[o], by = g_b1f[o + 1];
#pragma unroll
                for (int half = 0; half < 2; half++) {
                    int row = wm * 64 + mt * 16 + grp + half * 8;
                    if (row >= 1 && row <= 120 && ((row - 1) % 10) < 8) {
                        H1[(o >> 1) * RST + row] =
                            pkh(fmaxf(acc[mt][nt][half * 2] + bx, 0.f),
                                fmaxf(acc[mt][nt][half * 2 + 1] + by, 0.f));
                    }
                }
            }
    }
    __syncthreads();

    // conv2
    {
        float acc[4][2][4] = {};
        for (int dk = 0; dk < 3; dk++) {
            for (int ks = 0; ks < 4; ks++) {
                const uint32_t* p0 = H1 + (ks * 8 + qid) * RST + (dk - 1);
                const uint32_t* p4 = H1 + (ks * 8 + qid + 4) * RST + (dk - 1);
                uint32_t ah[4][4];
#pragma unroll
                for (int mt = 0; mt < 4; mt++) {
                    int m = wm * 64 + mt * 16 + grp;
                    ah[mt][0] = p0[m]; ah[mt][1] = p0[m + 8];
                    ah[mt][2] = p4[m]; ah[mt][3] = p4[m + 8];
                }
#pragma unroll
                for (int nt = 0; nt < 2; nt++) {
                    int oo = wn * 16 + nt * 8 + grp;
                    uint32_t b0 = __ldg(&g_c2p[dk * 2048 + (ks * 8 + qid) * 64 + oo]);
                    uint32_t b4 = __ldg(&g_c2p[dk * 2048 + (ks * 8 + qid + 4) * 64 + oo]);
#pragma unroll
                    for (int mt = 0; mt < 4; mt++)
                        mma_fp16(acc[mt][nt], ah[mt][0], ah[mt][1], ah[mt][2], ah[mt][3], b0, b4);
                }
            }
        }
        __syncthreads();
#pragma unroll
        for (int mt = 0; mt < 4; mt++)
#pragma unroll
            for (int nt = 0; nt < 2; nt++) {
                int o = wn * 16 + nt * 8 + qid * 2;
                float bx = g_b2f[o], by = g_b2f[o + 1];
#pragma unroll
                for (int half = 0; half < 2; half++) {
                    int row = wm * 64 + mt * 16 + grp + half * 8;
                    H2[(o >> 1) * RST + row] =
                        pkh(fmaxf(acc[mt][nt][half * 2] + bx, 0.f),
                            fmaxf(acc[mt][nt][half * 2 + 1] + by, 0.f));
                }
            }
    }
    __syncthreads();

    // conv3 + residual + ReLU
    {
        float acc[4][4][4] = {};
        for (int ks = 0; ks < 4; ks++) {
            const uint32_t* p0 = H2 + (ks * 8 + qid) * RST;
            const uint32_t* p4 = H2 + (ks * 8 + qid + 4) * RST;
            uint32_t ah[4][4];
#pragma unroll
            for (int mt = 0; mt < 4; mt++) {
                int m = wm * 64 + mt * 16 + grp;
                ah[mt][0] = p0[m]; ah[mt][1] = p0[m + 8];
                ah[mt][2] = p4[m]; ah[mt][3] = p4[m + 8];
            }
#pragma unroll
            for (int nt = 0; nt < 4; nt++) {
                int oo = wn * 32 + nt * 8 + grp;
                uint32_t b0 = __ldg(&g_c3p[(ks * 8 + qid) * 128 + oo]);
                uint32_t b4 = __ldg(&g_c3p[(ks * 8 + qid + 4) * 128 + oo]);
#pragma unroll
                for (int mt = 0; mt < 4; mt++)
                    mma_fp16(acc[mt][nt], ah[mt][0], ah[mt][1], ah[mt][2], ah[mt][3], b0, b4);
            }
        }
        __syncthreads();
#pragma unroll
        for (int nt = 0; nt < 4; nt++) {
            int oc = wn * 32 + nt * 8 + qid * 2;
            float cbx = __ldg(&conv3_b[oc]), cby = __ldg(&conv3_b[oc + 1]);
#pragma unroll
            for (int mt = 0; mt < 4; mt++)
#pragma unroll
                for (int half = 0; half < 2; half++) {
                    int row = wm * 64 + mt * 16 + grp + half * 8;
                    __half2 xv = *(__half2*)&XP[row * 128 + oc];
                    float y0 = fmaxf(__low2float(xv) + acc[mt][nt][half * 2] + cbx, 0.f);
                    float y1 = fmaxf(__high2float(xv) + acc[mt][nt][half * 2 + 1] + cby, 0.f);
                    *(float2*)&YB[row * 128 + oc] = make_float2(y0, y1);
                }
        }
    }
    __syncthreads();

    // fc2
    if (tid < NLC * 16) {
        int line = tid >> 4, sl = tid & 15;
        int n = n0 + line;
        float s0 = 0.f, s1 = 0.f, s2v = 0.f;
#pragma unroll
        for (int j = 0; j < 8; j++) {
            int c = sl * 8 + j;
            float yv[8];
#pragma unroll
            for (int t = 0; t < 8; t++) yv[t] = YB[(line * 10 + 1 + t) * 128 + c];
            int f = c * 8;
#pragma unroll
            for (int k = 0; k < 3; k++) {
                const float4* fw = (const float4*)(fc2_w + k * 1024 + f);
                float4 wa = __ldg(fw), wb = __ldg(fw + 1);
                float d = yv[0] * wa.x + yv[1] * wa.y + yv[2] * wa.z + yv[3] * wa.w
                        + yv[4] * wb.x + yv[5] * wb.y + yv[6] * wb.z + yv[7] * wb.w;
                if (k == 0) s0 += d; else if (k == 1) s1 += d; else s2v += d;
            }
        }
#pragma unroll
        for (int off = 8; off > 0; off >>= 1) {
            s0 += __shfl_down_sync(0xffffffffu, s0, off, 16);
            s1 += __shfl_down_sync(0xffffffffu, s1, off, 16);
            s2v += __shfl_down_sync(0xffffffffu, s2v, off, 16);
        }
        if (sl == 0 && n < NB * NL) {
            out[(size_t)n * 3 + 0] = s0 + __ldg(&fc2_b[0]);
            out[(size_t)n * 3 + 1] = s1 + __ldg(&fc2_b[1]);
            out[(size_t)n * 3 + 2] = s2v + __ldg(&fc2_b[2]);
        }
    }
}

// ---------------- launch ----------------
extern "C" void kernel_launch(void* const* d_in, const int* in_sizes, int n_in,
                              void* d_out, int out_size) {
    const float* feature = (const float*)d_in[0];
    const float* lines = (const float*)d_in[1];
    float* out = (float*)d_out;

    prep_kernel<<<64, 256>>>((const float*)d_in[2],
        (const float*)d_in[4], (const float*)d_in[5], (const float*)d_in[6], (const float*)d_in[7],
        (const float*)d_in[8], (const float*)d_in[9],
        (const float*)d_in[10], (const float*)d_in[11], (const float*)d_in[12], (const float*)d_in[13],
        (const float*)d_in[14], (const float*)d_in[15],
        (const float*)d_in[16], (const float*)d_in[17], (const float*)d_in[18], (const float*)d_in[19],
        (const float*)d_in[20]);
    fc1_tc_kernel<<<(NB * NPIX) / 128, 256>>>(feature, (const float*)d_in[3]);
    cudaFuncSetAttribute(line_kernel, cudaFuncAttributeMaxDynamicSharedMemorySize, LINE_SMEM);
    int nblk = (NB * NL + NLC - 1) / NLC;
    line_kernel<<<nblk, 256, LINE_SMEM>>>(lines, (const float*)d_in[21],
                                          (const float*)d_in[22], (const float*)d_in[23], out);
}